// round 12
// baseline (speedup 1.0000x reference)
#include <cuda_runtime.h>
#include <cuda_fp16.h>
#include <math.h>

#define N_NODES 10000
#define N_EDGES 320000
#define IN_DIM  512
#define H0      8
#define D0      64
#define F1      512   /* H0*D0 */
#define OUT_D   64
#define MAXD    128   /* fast-path degree cap (smem); slow path beyond */

// ---------------- scratch (device globals; no allocation allowed) ----------------
__device__ __half g_feat1h[N_NODES * F1];   // h @ W1 (fp16)
__device__ __half g_x1h   [N_NODES * F1];   // layer-1 output (fp16)
__device__ __half g_feat2h[N_NODES * OUT_D];
__device__ float  g_el1  [N_NODES * H0];
__device__ float  g_er1  [N_NODES * H0];
__device__ float  g_el2  [N_NODES];
__device__ float  g_er2  [N_NODES];
__device__ int    g_deg  [N_NODES];
__device__ int    g_cur  [N_NODES];
__device__ int    g_off  [N_NODES + 1];
__device__ int    g_csr  [N_EDGES];         // src ids sorted by dst

// ================= CSR build =================
__global__ void zero_deg(void) {
    int i = blockIdx.x * blockDim.x + threadIdx.x;
    if (i < N_NODES) g_deg[i] = 0;
}

__global__ void hist_kernel(const int4* __restrict__ dst4) {
    int i = blockIdx.x * blockDim.x + threadIdx.x;
    if (i < N_EDGES / 4) {
        int4 d = dst4[i];
        atomicAdd(&g_deg[d.x], 1);
        atomicAdd(&g_deg[d.y], 1);
        atomicAdd(&g_deg[d.z], 1);
        atomicAdd(&g_deg[d.w], 1);
    }
}

__global__ void __launch_bounds__(1024) scan_kernel(void) {
    __shared__ int part[1024];
    int tid = threadIdx.x;
    int base = tid * 10;
    int sum = 0;
#pragma unroll
    for (int j = 0; j < 10; j++) {
        int idx = base + j;
        if (idx < N_NODES) sum += g_deg[idx];
    }
    part[tid] = sum;
    __syncthreads();
    for (int off = 1; off < 1024; off <<= 1) {
        int v = (tid >= off) ? part[tid - off] : 0;
        __syncthreads();
        part[tid] += v;
        __syncthreads();
    }
    int run = (tid > 0) ? part[tid - 1] : 0;
#pragma unroll
    for (int j = 0; j < 10; j++) {
        int idx = base + j;
        if (idx < N_NODES) {
            int v = g_deg[idx];
            g_off[idx] = run;
            g_cur[idx] = run;
            run += v;
        }
    }
    if (tid == 1023) g_off[N_NODES] = part[1023];
}

__global__ void scatter_kernel(const int4* __restrict__ src4, const int4* __restrict__ dst4) {
    int i = blockIdx.x * blockDim.x + threadIdx.x;
    if (i < N_EDGES / 4) {
        int4 s = src4[i];
        int4 d = dst4[i];
        int p0 = atomicAdd(&g_cur[d.x], 1);
        int p1 = atomicAdd(&g_cur[d.y], 1);
        int p2 = atomicAdd(&g_cur[d.z], 1);
        int p3 = atomicAdd(&g_cur[d.w], 1);
        g_csr[p0] = s.x; g_csr[p1] = s.y; g_csr[p2] = s.z; g_csr[p3] = s.w;
    }
}

// ================= tf32 GEMM + fused attention-logit epilogue =================
// C[M,N](fp16) = A[M,K] @ B[K,N];  BM=128, BN=64, BK=16; 128 thr = 4 warps (2x2).
// BN == head dim (64): block (m0, hh) holds head hh fully -> epilogue reduces
// el/er = feat . attn_{l,r}[hh] for its 128 rows and writes el_out/er_out.
__device__ __forceinline__ unsigned f2tf32(float f) {
    unsigned u;
    asm("cvt.rna.tf32.f32 %0, %1;" : "=r"(u) : "f"(f));
    return u;
}

template<typename AT>
__device__ __forceinline__ void load_tiles(
    const AT* __restrict__ A, const float* __restrict__ B,
    int M, int N, int K, int m0, int n0, int k0,
    int arow, int acol, int brow, int bcol, float4* pa, float4* pb)
{
#pragma unroll
    for (int j = 0; j < 4; j++) {
        int r = m0 + arow + j * 32;
        if (r < M) {
            if constexpr (sizeof(AT) == 4) {
                pa[j] = *(const float4*)&A[(size_t)r * K + k0 + acol];
            } else {
                uint2 u = *(const uint2*)&A[(size_t)r * K + k0 + acol];
                float2 f0 = __half22float2(*reinterpret_cast<__half2*>(&u.x));
                float2 f1 = __half22float2(*reinterpret_cast<__half2*>(&u.y));
                pa[j] = make_float4(f0.x, f0.y, f1.x, f1.y);
            }
        } else pa[j] = make_float4(0.f, 0.f, 0.f, 0.f);
    }
#pragma unroll
    for (int j = 0; j < 2; j++)
        pb[j] = *(const float4*)&B[(size_t)(k0 + brow) * N + n0 + bcol + j * 4];
}

template<typename AT>
__global__ void __launch_bounds__(128)
gemm_attn(const AT* __restrict__ A, const float* __restrict__ B,
          __half* __restrict__ C, int M, int N, int K,
          const float* __restrict__ al, const float* __restrict__ ar,
          float* __restrict__ el_out, float* __restrict__ er_out, int Hs)
{
    __shared__ unsigned As[2][128][20];
    __shared__ unsigned Bs[2][16][68];
    __shared__ float s_el[2][128], s_er[2][128];
    const int tid  = threadIdx.x;
    const int lane = tid & 31, warp = tid >> 5;
    const int wm = warp >> 1, wn = warp & 1;
    const int gid = lane >> 2, tig = lane & 3;
    const int m0 = blockIdx.x * 128, n0 = blockIdx.y * 64;
    const int hh = blockIdx.y;   // head index (BN == head dim)

    const int arow = tid >> 2;
    const int acol = (tid & 3) * 4;
    const int brow = tid >> 3;
    const int bcol = (tid & 7) * 8;

    float acc[4][4][4];
#pragma unroll
    for (int mi = 0; mi < 4; mi++)
#pragma unroll
        for (int ni = 0; ni < 4; ni++)
#pragma unroll
            for (int q = 0; q < 4; q++) acc[mi][ni][q] = 0.f;

    float4 pa[4], pb[2];
    load_tiles<AT>(A, B, M, N, K, m0, n0, 0, arow, acol, brow, bcol, pa, pb);
#pragma unroll
    for (int j = 0; j < 4; j++) {
        int r = arow + j * 32;
        As[0][r][acol + 0] = f2tf32(pa[j].x);
        As[0][r][acol + 1] = f2tf32(pa[j].y);
        As[0][r][acol + 2] = f2tf32(pa[j].z);
        As[0][r][acol + 3] = f2tf32(pa[j].w);
    }
#pragma unroll
    for (int j = 0; j < 2; j++) {
        Bs[0][brow][bcol + j * 4 + 0] = f2tf32(pb[j].x);
        Bs[0][brow][bcol + j * 4 + 1] = f2tf32(pb[j].y);
        Bs[0][brow][bcol + j * 4 + 2] = f2tf32(pb[j].z);
        Bs[0][brow][bcol + j * 4 + 3] = f2tf32(pb[j].w);
    }
    __syncthreads();

    int cur = 0;
    for (int k0 = 0; k0 < K; k0 += 16) {
        const bool more = (k0 + 16 < K);
        if (more)
            load_tiles<AT>(A, B, M, N, K, m0, n0, k0 + 16, arow, acol, brow, bcol, pa, pb);

#pragma unroll
        for (int kk = 0; kk < 2; kk++) {
            unsigned af[4][4], bf[4][2];
#pragma unroll
            for (int mi = 0; mi < 4; mi++) {
                int r = wm * 64 + mi * 16 + gid;
                af[mi][0] = As[cur][r    ][kk * 8 + tig];
                af[mi][1] = As[cur][r + 8][kk * 8 + tig];
                af[mi][2] = As[cur][r    ][kk * 8 + tig + 4];
                af[mi][3] = As[cur][r + 8][kk * 8 + tig + 4];
            }
#pragma unroll
            for (int ni = 0; ni < 4; ni++) {
                int c = wn * 32 + ni * 8 + gid;
                bf[ni][0] = Bs[cur][kk * 8 + tig    ][c];
                bf[ni][1] = Bs[cur][kk * 8 + tig + 4][c];
            }
#pragma unroll
            for (int mi = 0; mi < 4; mi++)
#pragma unroll
                for (int ni = 0; ni < 4; ni++) {
                    asm volatile(
                        "mma.sync.aligned.m16n8k8.row.col.f32.tf32.tf32.f32 "
                        "{%0,%1,%2,%3}, {%4,%5,%6,%7}, {%8,%9}, {%0,%1,%2,%3};"
                        : "+f"(acc[mi][ni][0]), "+f"(acc[mi][ni][1]),
                          "+f"(acc[mi][ni][2]), "+f"(acc[mi][ni][3])
                        : "r"(af[mi][0]), "r"(af[mi][1]), "r"(af[mi][2]), "r"(af[mi][3]),
                          "r"(bf[ni][0]), "r"(bf[ni][1]));
                }
        }

        if (more) {
            int nxt = cur ^ 1;
#pragma unroll
            for (int j = 0; j < 4; j++) {
                int r = arow + j * 32;
                As[nxt][r][acol + 0] = f2tf32(pa[j].x);
                As[nxt][r][acol + 1] = f2tf32(pa[j].y);
                As[nxt][r][acol + 2] = f2tf32(pa[j].z);
                As[nxt][r][acol + 3] = f2tf32(pa[j].w);
            }
#pragma unroll
            for (int j = 0; j < 2; j++) {
                Bs[nxt][brow][bcol + j * 4 + 0] = f2tf32(pb[j].x);
                Bs[nxt][brow][bcol + j * 4 + 1] = f2tf32(pb[j].y);
                Bs[nxt][brow][bcol + j * 4 + 2] = f2tf32(pb[j].z);
                Bs[nxt][brow][bcol + j * 4 + 3] = f2tf32(pb[j].w);
            }
            __syncthreads();
            cur = nxt;
        }
    }

    // ---- C store (fp16) ----
#pragma unroll
    for (int mi = 0; mi < 4; mi++)
#pragma unroll
        for (int ni = 0; ni < 4; ni++) {
            int r = m0 + wm * 64 + mi * 16 + gid;
            int c = n0 + wn * 32 + ni * 8 + 2 * tig;
            if (r < M)
                *(__half2*)&C[(size_t)r * N + c] =
                    __floats2half2_rn(acc[mi][ni][0], acc[mi][ni][1]);
            if (r + 8 < M)
                *(__half2*)&C[(size_t)(r + 8) * N + c] =
                    __floats2half2_rn(acc[mi][ni][2], acc[mi][ni][3]);
        }

    // ---- fused attention logits: el/er = feat . attn_{l,r}[hh] ----
#pragma unroll
    for (int mi = 0; mi < 4; mi++) {
        float el0 = 0.f, er0 = 0.f, el1 = 0.f, er1 = 0.f;
#pragma unroll
        for (int ni = 0; ni < 4; ni++) {
            int cl = wn * 32 + ni * 8 + 2 * tig;
            float A0 = al[hh * 64 + cl], A1 = al[hh * 64 + cl + 1];
            float R0 = ar[hh * 64 + cl], R1 = ar[hh * 64 + cl + 1];
            el0 = fmaf(acc[mi][ni][0], A0, fmaf(acc[mi][ni][1], A1, el0));
            er0 = fmaf(acc[mi][ni][0], R0, fmaf(acc[mi][ni][1], R1, er0));
            el1 = fmaf(acc[mi][ni][2], A0, fmaf(acc[mi][ni][3], A1, el1));
            er1 = fmaf(acc[mi][ni][2], R0, fmaf(acc[mi][ni][3], R1, er1));
        }
#pragma unroll
        for (int o = 1; o <= 2; o <<= 1) {
            el0 += __shfl_xor_sync(0xffffffffu, el0, o);
            er0 += __shfl_xor_sync(0xffffffffu, er0, o);
            el1 += __shfl_xor_sync(0xffffffffu, el1, o);
            er1 += __shfl_xor_sync(0xffffffffu, er1, o);
        }
        if (tig == 0) {
            int r = wm * 64 + mi * 16 + gid;
            s_el[wn][r]     = el0;  s_er[wn][r]     = er0;
            s_el[wn][r + 8] = el1;  s_er[wn][r + 8] = er1;
        }
    }
    __syncthreads();
    {
        int r = tid;
        if (m0 + r < M) {
            el_out[(size_t)(m0 + r) * Hs + hh] = s_el[0][r] + s_el[1][r];
            er_out[(size_t)(m0 + r) * Hs + hh] = s_er[0][r] + s_er[1][r];
        }
    }
}

// ================= fused per-node aggregation, layer 1 =================
__global__ void __launch_bounds__(128)
node_agg1(void) {
    int n   = blockIdx.x;
    int tid = threadIdx.x;
    __shared__ int   s_src[MAXD];
    __shared__ float s_w[MAXD][H0];
    __shared__ float s_red[16][H0];
    __shared__ float s_mh[H0], s_inv[H0], s_er[H0];
    int beg = g_off[n], deg = g_off[n + 1] - beg;
    if (tid < 8) s_er[tid] = g_er1[n * H0 + tid];

    if (deg <= MAXD) {
        if (tid < deg) s_src[tid] = g_csr[beg + tid];
        __syncthreads();
        int h = tid & 7, r = tid >> 3;   // r in 0..15
        float lmax = -1e30f;
        for (int j = r; j < deg; j += 16) {
            float x = g_el1[s_src[j] * H0 + h] + s_er[h];
            x = x > 0.f ? x : 0.2f * x;
            s_w[j][h] = x;
            lmax = fmaxf(lmax, x);
        }
        s_red[r][h] = lmax;
        __syncthreads();
        if (tid < 8) {
            float m = s_red[0][tid];
#pragma unroll
            for (int q = 1; q < 16; q++) m = fmaxf(m, s_red[q][tid]);
            s_mh[tid] = m;
        }
        __syncthreads();
        float mh = s_mh[h];
        float lsum = 0.f;
        for (int j = r; j < deg; j += 16) {
            float w = __expf(s_w[j][h] - mh);
            s_w[j][h] = w;
            lsum += w;
        }
        s_red[r][h] = lsum;
        __syncthreads();
        if (tid < 8) {
            float s = 0.f;
#pragma unroll
            for (int q = 0; q < 16; q++) s += s_red[q][tid];
            s_inv[tid] = (deg > 0) ? 1.f / s : 0.f;
        }
        __syncthreads();

        int h2 = tid >> 4;
        const int col = tid * 4;
        float4 acc = make_float4(0.f, 0.f, 0.f, 0.f);
#pragma unroll 4
        for (int j = 0; j < deg; j++) {
            float w = s_w[j][h2];
            uint2 u = *(const uint2*)&g_feat1h[(size_t)s_src[j] * F1 + col];
            float2 f0 = __half22float2(*reinterpret_cast<__half2*>(&u.x));
            float2 f1 = __half22float2(*reinterpret_cast<__half2*>(&u.y));
            acc.x = fmaf(w, f0.x, acc.x);
            acc.y = fmaf(w, f0.y, acc.y);
            acc.z = fmaf(w, f1.x, acc.z);
            acc.w = fmaf(w, f1.y, acc.w);
        }
        float inv = s_inv[h2];
        float4 o;
        o.x = acc.x * inv; o.y = acc.y * inv; o.z = acc.z * inv; o.w = acc.w * inv;
        o.x = o.x > 0.f ? o.x : expm1f(o.x);
        o.y = o.y > 0.f ? o.y : expm1f(o.y);
        o.z = o.z > 0.f ? o.z : expm1f(o.z);
        o.w = o.w > 0.f ? o.w : expm1f(o.w);
        uint2 uo;
        *reinterpret_cast<__half2*>(&uo.x) = __floats2half2_rn(o.x, o.y);
        *reinterpret_cast<__half2*>(&uo.y) = __floats2half2_rn(o.z, o.w);
        *(uint2*)&g_x1h[(size_t)n * F1 + col] = uo;
    } else {
        __syncthreads();
        const int* sp = g_csr + beg;
        int h = tid >> 4;
        float erh = s_er[h];
        float m = -1e30f;
        for (int j = 0; j < deg; j++) {
            float x = g_el1[sp[j] * H0 + h] + erh;
            x = x > 0.f ? x : 0.2f * x;
            m = fmaxf(m, x);
        }
        float4 acc = make_float4(0.f, 0.f, 0.f, 0.f);
        float s = 0.f;
        const int col = tid * 4;
        for (int j = 0; j < deg; j++) {
            int si = sp[j];
            float x = g_el1[si * H0 + h] + erh;
            x = x > 0.f ? x : 0.2f * x;
            float w = __expf(x - m);
            s += w;
            uint2 u = *(const uint2*)&g_feat1h[(size_t)si * F1 + col];
            float2 f0 = __half22float2(*reinterpret_cast<__half2*>(&u.x));
            float2 f1 = __half22float2(*reinterpret_cast<__half2*>(&u.y));
            acc.x = fmaf(w, f0.x, acc.x);
            acc.y = fmaf(w, f0.y, acc.y);
            acc.z = fmaf(w, f1.x, acc.z);
            acc.w = fmaf(w, f1.y, acc.w);
        }
        float inv = 1.f / s;
        float4 o;
        o.x = acc.x * inv; o.y = acc.y * inv; o.z = acc.z * inv; o.w = acc.w * inv;
        o.x = o.x > 0.f ? o.x : expm1f(o.x);
        o.y = o.y > 0.f ? o.y : expm1f(o.y);
        o.z = o.z > 0.f ? o.z : expm1f(o.z);
        o.w = o.w > 0.f ? o.w : expm1f(o.w);
        uint2 uo;
        *reinterpret_cast<__half2*>(&uo.x) = __floats2half2_rn(o.x, o.y);
        *reinterpret_cast<__half2*>(&uo.y) = __floats2half2_rn(o.z, o.w);
        *(uint2*)&g_x1h[(size_t)n * F1 + col] = uo;
    }
}

// ================= fused per-node aggregation, layer 2 (writes d_out) =================
__global__ void __launch_bounds__(64)
node_agg2(float* __restrict__ out) {
    int n = blockIdx.x, tid = threadIdx.x;
    __shared__ int   s_src[MAXD];
    __shared__ float s_w[MAXD];
    __shared__ float s_red[2];
    int beg = g_off[n], deg = g_off[n + 1] - beg;
    float er = g_er2[n];

    if (deg <= MAXD) {
        for (int i = tid; i < deg; i += 64) s_src[i] = g_csr[beg + i];
        __syncthreads();
        float lmax = -1e30f;
        for (int j = tid; j < deg; j += 64) {
            float x = g_el2[s_src[j]] + er;
            x = x > 0.f ? x : 0.2f * x;
            s_w[j] = x;
            lmax = fmaxf(lmax, x);
        }
#pragma unroll
        for (int o = 16; o > 0; o >>= 1)
            lmax = fmaxf(lmax, __shfl_xor_sync(0xffffffffu, lmax, o));
        if ((tid & 31) == 0) s_red[tid >> 5] = lmax;
        __syncthreads();
        float m = fmaxf(s_red[0], s_red[1]);
        float lsum = 0.f;
        for (int j = tid; j < deg; j += 64) {
            float w = __expf(s_w[j] - m);
            s_w[j] = w;
            lsum += w;
        }
#pragma unroll
        for (int o = 16; o > 0; o >>= 1)
            lsum += __shfl_xor_sync(0xffffffffu, lsum, o);
        if ((tid & 31) == 0) s_red[tid >> 5] = lsum;
        __syncthreads();
        float s = s_red[0] + s_red[1];

        float acc = 0.f;
#pragma unroll 4
        for (int j = 0; j < deg; j++)
            acc = fmaf(s_w[j], __half2float(g_feat2h[(size_t)s_src[j] * OUT_D + tid]), acc);
        out[(size_t)n * OUT_D + tid] = (deg > 0) ? acc / s : 0.f;
    } else {
        __syncthreads();
        const int* sp = g_csr + beg;
        float m = -1e30f;
        for (int j = 0; j < deg; j++) {
            float x = g_el2[sp[j]] + er;
            x = x > 0.f ? x : 0.2f * x;
            m = fmaxf(m, x);
        }
        float acc = 0.f, s = 0.f;
        for (int j = 0; j < deg; j++) {
            int si = sp[j];
            float x = g_el2[si] + er;
            x = x > 0.f ? x : 0.2f * x;
            float w = __expf(x - m);
            s += w;
            acc = fmaf(w, __half2float(g_feat2h[(size_t)si * OUT_D + tid]), acc);
        }
        out[(size_t)n * OUT_D + tid] = acc / s;
    }
}

// ================= launch =================
extern "C" void kernel_launch(void* const* d_in, const int* in_sizes, int n_in,
                              void* d_out, int out_size) {
    (void)in_sizes; (void)n_in; (void)out_size;
    const float* h   = (const float*)d_in[0];
    const int*   src = (const int*)  d_in[1];
    const int*   dst = (const int*)  d_in[2];
    const float* W1  = (const float*)d_in[3];
    const float* al1 = (const float*)d_in[4];
    const float* ar1 = (const float*)d_in[5];
    const float* W2  = (const float*)d_in[6];
    const float* al2 = (const float*)d_in[7];
    const float* ar2 = (const float*)d_in[8];
    float* out = (float*)d_out;

    __half *p_feat1h, *p_x1h, *p_feat2h;
    float *p_el1, *p_er1, *p_el2, *p_er2;
    cudaGetSymbolAddress((void**)&p_feat1h, g_feat1h);
    cudaGetSymbolAddress((void**)&p_x1h,    g_x1h);
    cudaGetSymbolAddress((void**)&p_feat2h, g_feat2h);
    cudaGetSymbolAddress((void**)&p_el1,    g_el1);
    cudaGetSymbolAddress((void**)&p_er1,    g_er1);
    cudaGetSymbolAddress((void**)&p_el2,    g_el2);
    cudaGetSymbolAddress((void**)&p_er2,    g_er2);

    // ---- CSR build (shared by both layers) ----
    zero_deg<<<(N_NODES + 255) / 256, 256>>>();
    hist_kernel<<<(N_EDGES / 4 + 255) / 256, 256>>>((const int4*)dst);
    scan_kernel<<<1, 1024>>>();
    scatter_kernel<<<(N_EDGES / 4 + 255) / 256, 256>>>((const int4*)src, (const int4*)dst);

    // ---- layer 1 ----
    gemm_attn<float><<<dim3((N_NODES + 127) / 128, F1 / 64), 128>>>(
        h, W1, p_feat1h, N_NODES, F1, IN_DIM, al1, ar1, p_el1, p_er1, H0);
    node_agg1<<<N_NODES, 128>>>();

    // ---- layer 2 ----
    gemm_attn<__half><<<dim3((N_NODES + 127) / 128, OUT_D / 64), 128>>>(
        p_x1h, W2, p_feat2h, N_NODES, OUT_D, F1, al2, ar2, p_el2, p_er2, 1);
    node_agg2<<<N_NODES, 64>>>(out);
}

// round 13
// speedup vs baseline: 1.0093x; 1.0093x over previous
#include <cuda_runtime.h>
#include <cuda_fp16.h>
#include <math.h>

#define N_NODES 10000
#define N_EDGES 320000
#define IN_DIM  512
#define H0      8
#define D0      64
#define F1      512   /* H0*D0 */
#define OUT_D   64
#define MAXD    128   /* fast-path degree cap (smem); slow path beyond */

// ---------------- scratch (device globals; no allocation allowed) ----------------
__device__ __half g_feat1h[N_NODES * F1];   // h @ W1 (fp16)
__device__ __half g_x1h   [N_NODES * F1];   // layer-1 output (fp16)
__device__ __half g_feat2h[N_NODES * OUT_D];
__device__ float  g_el1  [N_NODES * H0];
__device__ float  g_er1  [N_NODES * H0];
__device__ float  g_el2  [N_NODES];
__device__ float  g_er2  [N_NODES];
__device__ int    g_deg  [N_NODES];
__device__ int    g_cur  [N_NODES];
__device__ int    g_off  [N_NODES + 1];
__device__ int    g_csr  [N_EDGES];         // src ids sorted by dst

// ================= CSR build =================
__global__ void zero_deg(void) {
    int i = blockIdx.x * blockDim.x + threadIdx.x;
    if (i < N_NODES) g_deg[i] = 0;
}

__global__ void hist_kernel(const int4* __restrict__ dst4) {
    int i = blockIdx.x * blockDim.x + threadIdx.x;
    if (i < N_EDGES / 4) {
        int4 d = dst4[i];
        atomicAdd(&g_deg[d.x], 1);
        atomicAdd(&g_deg[d.y], 1);
        atomicAdd(&g_deg[d.z], 1);
        atomicAdd(&g_deg[d.w], 1);
    }
}

__global__ void __launch_bounds__(1024) scan_kernel(void) {
    __shared__ int part[1024];
    int tid = threadIdx.x;
    int base = tid * 10;
    int sum = 0;
#pragma unroll
    for (int j = 0; j < 10; j++) {
        int idx = base + j;
        if (idx < N_NODES) sum += g_deg[idx];
    }
    part[tid] = sum;
    __syncthreads();
    for (int off = 1; off < 1024; off <<= 1) {
        int v = (tid >= off) ? part[tid - off] : 0;
        __syncthreads();
        part[tid] += v;
        __syncthreads();
    }
    int run = (tid > 0) ? part[tid - 1] : 0;
#pragma unroll
    for (int j = 0; j < 10; j++) {
        int idx = base + j;
        if (idx < N_NODES) {
            int v = g_deg[idx];
            g_off[idx] = run;
            g_cur[idx] = run;
            run += v;
        }
    }
    if (tid == 1023) g_off[N_NODES] = part[1023];
}

__global__ void scatter_kernel(const int4* __restrict__ src4, const int4* __restrict__ dst4) {
    int i = blockIdx.x * blockDim.x + threadIdx.x;
    if (i < N_EDGES / 4) {
        int4 s = src4[i];
        int4 d = dst4[i];
        int p0 = atomicAdd(&g_cur[d.x], 1);
        int p1 = atomicAdd(&g_cur[d.y], 1);
        int p2 = atomicAdd(&g_cur[d.z], 1);
        int p3 = atomicAdd(&g_cur[d.w], 1);
        g_csr[p0] = s.x; g_csr[p1] = s.y; g_csr[p2] = s.z; g_csr[p3] = s.w;
    }
}

// ================= tf32 GEMM + fused attention-logit epilogue =================
// C[M,N](fp16) = A[M,K] @ B[K,N];  BM=128, BN=64, BK=16; 128 thr = 4 warps (2x2).
// BN == head dim (64): block (m0, hh) holds head hh fully -> epilogue reduces
// el/er = feat . attn_{l,r}[hh] for its 128 rows and writes el_out/er_out.
__device__ __forceinline__ unsigned f2tf32(float f) {
    unsigned u;
    asm("cvt.rna.tf32.f32 %0, %1;" : "=r"(u) : "f"(f));
    return u;
}

template<typename AT>
__device__ __forceinline__ void load_tiles(
    const AT* __restrict__ A, const float* __restrict__ B,
    int M, int N, int K, int m0, int n0, int k0,
    int arow, int acol, int brow, int bcol, float4* pa, float4* pb)
{
#pragma unroll
    for (int j = 0; j < 4; j++) {
        int r = m0 + arow + j * 32;
        if (r < M) {
            if constexpr (sizeof(AT) == 4) {
                pa[j] = *(const float4*)&A[(size_t)r * K + k0 + acol];
            } else {
                uint2 u = *(const uint2*)&A[(size_t)r * K + k0 + acol];
                float2 f0 = __half22float2(*reinterpret_cast<__half2*>(&u.x));
                float2 f1 = __half22float2(*reinterpret_cast<__half2*>(&u.y));
                pa[j] = make_float4(f0.x, f0.y, f1.x, f1.y);
            }
        } else pa[j] = make_float4(0.f, 0.f, 0.f, 0.f);
    }
#pragma unroll
    for (int j = 0; j < 2; j++)
        pb[j] = *(const float4*)&B[(size_t)(k0 + brow) * N + n0 + bcol + j * 4];
}

template<typename AT>
__global__ void __launch_bounds__(128)
gemm_attn(const AT* __restrict__ A, const float* __restrict__ B,
          __half* __restrict__ C, int M, int N, int K,
          const float* __restrict__ al, const float* __restrict__ ar,
          float* __restrict__ el_out, float* __restrict__ er_out, int Hs)
{
    __shared__ unsigned As[2][128][20];
    __shared__ unsigned Bs[2][16][68];
    __shared__ float s_el[2][128], s_er[2][128];
    const int tid  = threadIdx.x;
    const int lane = tid & 31, warp = tid >> 5;
    const int wm = warp >> 1, wn = warp & 1;
    const int gid = lane >> 2, tig = lane & 3;
    const int m0 = blockIdx.x * 128, n0 = blockIdx.y * 64;
    const int hh = blockIdx.y;   // head index (BN == head dim)

    const int arow = tid >> 2;
    const int acol = (tid & 3) * 4;
    const int brow = tid >> 3;
    const int bcol = (tid & 7) * 8;

    float acc[4][4][4];
#pragma unroll
    for (int mi = 0; mi < 4; mi++)
#pragma unroll
        for (int ni = 0; ni < 4; ni++)
#pragma unroll
            for (int q = 0; q < 4; q++) acc[mi][ni][q] = 0.f;

    float4 pa[4], pb[2];
    load_tiles<AT>(A, B, M, N, K, m0, n0, 0, arow, acol, brow, bcol, pa, pb);
#pragma unroll
    for (int j = 0; j < 4; j++) {
        int r = arow + j * 32;
        As[0][r][acol + 0] = f2tf32(pa[j].x);
        As[0][r][acol + 1] = f2tf32(pa[j].y);
        As[0][r][acol + 2] = f2tf32(pa[j].z);
        As[0][r][acol + 3] = f2tf32(pa[j].w);
    }
#pragma unroll
    for (int j = 0; j < 2; j++) {
        Bs[0][brow][bcol + j * 4 + 0] = f2tf32(pb[j].x);
        Bs[0][brow][bcol + j * 4 + 1] = f2tf32(pb[j].y);
        Bs[0][brow][bcol + j * 4 + 2] = f2tf32(pb[j].z);
        Bs[0][brow][bcol + j * 4 + 3] = f2tf32(pb[j].w);
    }
    __syncthreads();

    int cur = 0;
    for (int k0 = 0; k0 < K; k0 += 16) {
        const bool more = (k0 + 16 < K);
        if (more)
            load_tiles<AT>(A, B, M, N, K, m0, n0, k0 + 16, arow, acol, brow, bcol, pa, pb);

#pragma unroll
        for (int kk = 0; kk < 2; kk++) {
            unsigned af[4][4], bf[4][2];
#pragma unroll
            for (int mi = 0; mi < 4; mi++) {
                int r = wm * 64 + mi * 16 + gid;
                af[mi][0] = As[cur][r    ][kk * 8 + tig];
                af[mi][1] = As[cur][r + 8][kk * 8 + tig];
                af[mi][2] = As[cur][r    ][kk * 8 + tig + 4];
                af[mi][3] = As[cur][r + 8][kk * 8 + tig + 4];
            }
#pragma unroll
            for (int ni = 0; ni < 4; ni++) {
                int c = wn * 32 + ni * 8 + gid;
                bf[ni][0] = Bs[cur][kk * 8 + tig    ][c];
                bf[ni][1] = Bs[cur][kk * 8 + tig + 4][c];
            }
#pragma unroll
            for (int mi = 0; mi < 4; mi++)
#pragma unroll
                for (int ni = 0; ni < 4; ni++) {
                    asm volatile(
                        "mma.sync.aligned.m16n8k8.row.col.f32.tf32.tf32.f32 "
                        "{%0,%1,%2,%3}, {%4,%5,%6,%7}, {%8,%9}, {%0,%1,%2,%3};"
                        : "+f"(acc[mi][ni][0]), "+f"(acc[mi][ni][1]),
                          "+f"(acc[mi][ni][2]), "+f"(acc[mi][ni][3])
                        : "r"(af[mi][0]), "r"(af[mi][1]), "r"(af[mi][2]), "r"(af[mi][3]),
                          "r"(bf[ni][0]), "r"(bf[ni][1]));
                }
        }

        if (more) {
            int nxt = cur ^ 1;
#pragma unroll
            for (int j = 0; j < 4; j++) {
                int r = arow + j * 32;
                As[nxt][r][acol + 0] = f2tf32(pa[j].x);
                As[nxt][r][acol + 1] = f2tf32(pa[j].y);
                As[nxt][r][acol + 2] = f2tf32(pa[j].z);
                As[nxt][r][acol + 3] = f2tf32(pa[j].w);
            }
#pragma unroll
            for (int j = 0; j < 2; j++) {
                Bs[nxt][brow][bcol + j * 4 + 0] = f2tf32(pb[j].x);
                Bs[nxt][brow][bcol + j * 4 + 1] = f2tf32(pb[j].y);
                Bs[nxt][brow][bcol + j * 4 + 2] = f2tf32(pb[j].z);
                Bs[nxt][brow][bcol + j * 4 + 3] = f2tf32(pb[j].w);
            }
            __syncthreads();
            cur = nxt;
        }
    }

    // ---- C store (fp16) ----
#pragma unroll
    for (int mi = 0; mi < 4; mi++)
#pragma unroll
        for (int ni = 0; ni < 4; ni++) {
            int r = m0 + wm * 64 + mi * 16 + gid;
            int c = n0 + wn * 32 + ni * 8 + 2 * tig;
            if (r < M)
                *(__half2*)&C[(size_t)r * N + c] =
                    __floats2half2_rn(acc[mi][ni][0], acc[mi][ni][1]);
            if (r + 8 < M)
                *(__half2*)&C[(size_t)(r + 8) * N + c] =
                    __floats2half2_rn(acc[mi][ni][2], acc[mi][ni][3]);
        }

    // ---- fused attention logits: el/er = feat . attn_{l,r}[hh] ----
#pragma unroll
    for (int mi = 0; mi < 4; mi++) {
        float el0 = 0.f, er0 = 0.f, el1 = 0.f, er1 = 0.f;
#pragma unroll
        for (int ni = 0; ni < 4; ni++) {
            int cl = wn * 32 + ni * 8 + 2 * tig;
            float A0 = al[hh * 64 + cl], A1 = al[hh * 64 + cl + 1];
            float R0 = ar[hh * 64 + cl], R1 = ar[hh * 64 + cl + 1];
            el0 = fmaf(acc[mi][ni][0], A0, fmaf(acc[mi][ni][1], A1, el0));
            er0 = fmaf(acc[mi][ni][0], R0, fmaf(acc[mi][ni][1], R1, er0));
            el1 = fmaf(acc[mi][ni][2], A0, fmaf(acc[mi][ni][3], A1, el1));
            er1 = fmaf(acc[mi][ni][2], R0, fmaf(acc[mi][ni][3], R1, er1));
        }
#pragma unroll
        for (int o = 1; o <= 2; o <<= 1) {
            el0 += __shfl_xor_sync(0xffffffffu, el0, o);
            er0 += __shfl_xor_sync(0xffffffffu, er0, o);
            el1 += __shfl_xor_sync(0xffffffffu, el1, o);
            er1 += __shfl_xor_sync(0xffffffffu, er1, o);
        }
        if (tig == 0) {
            int r = wm * 64 + mi * 16 + gid;
            s_el[wn][r]     = el0;  s_er[wn][r]     = er0;
            s_el[wn][r + 8] = el1;  s_er[wn][r + 8] = er1;
        }
    }
    __syncthreads();
    {
        int r = tid;
        if (m0 + r < M) {
            el_out[(size_t)(m0 + r) * Hs + hh] = s_el[0][r] + s_el[1][r];
            er_out[(size_t)(m0 + r) * Hs + hh] = s_er[0][r] + s_er[1][r];
        }
    }
}

// ================= fused per-node aggregation, layer 1 =================
__global__ void __launch_bounds__(128)
node_agg1(void) {
    int n   = blockIdx.x;
    int tid = threadIdx.x;
    __shared__ int   s_src[MAXD];
    __shared__ float s_w[MAXD][H0];
    __shared__ float s_red[16][H0];
    __shared__ float s_mh[H0], s_inv[H0], s_er[H0];
    int beg = g_off[n], deg = g_off[n + 1] - beg;
    if (tid < 8) s_er[tid] = g_er1[n * H0 + tid];

    if (deg <= MAXD) {
        if (tid < deg) s_src[tid] = g_csr[beg + tid];
        __syncthreads();
        int h = tid & 7, r = tid >> 3;   // r in 0..15
        float lmax = -1e30f;
        for (int j = r; j < deg; j += 16) {
            float x = g_el1[s_src[j] * H0 + h] + s_er[h];
            x = x > 0.f ? x : 0.2f * x;
            s_w[j][h] = x;
            lmax = fmaxf(lmax, x);
        }
        s_red[r][h] = lmax;
        __syncthreads();
        if (tid < 8) {
            float m = s_red[0][tid];
#pragma unroll
            for (int q = 1; q < 16; q++) m = fmaxf(m, s_red[q][tid]);
            s_mh[tid] = m;
        }
        __syncthreads();
        float mh = s_mh[h];
        float lsum = 0.f;
        for (int j = r; j < deg; j += 16) {
            float w = __expf(s_w[j][h] - mh);
            s_w[j][h] = w;
            lsum += w;
        }
        s_red[r][h] = lsum;
        __syncthreads();
        if (tid < 8) {
            float s = 0.f;
#pragma unroll
            for (int q = 0; q < 16; q++) s += s_red[q][tid];
            s_inv[tid] = (deg > 0) ? 1.f / s : 0.f;
        }
        __syncthreads();

        int h2 = tid >> 4;
        const int col = tid * 4;
        float4 acc = make_float4(0.f, 0.f, 0.f, 0.f);
#pragma unroll 4
        for (int j = 0; j < deg; j++) {
            float w = s_w[j][h2];
            uint2 u = *(const uint2*)&g_feat1h[(size_t)s_src[j] * F1 + col];
            float2 f0 = __half22float2(*reinterpret_cast<__half2*>(&u.x));
            float2 f1 = __half22float2(*reinterpret_cast<__half2*>(&u.y));
            acc.x = fmaf(w, f0.x, acc.x);
            acc.y = fmaf(w, f0.y, acc.y);
            acc.z = fmaf(w, f1.x, acc.z);
            acc.w = fmaf(w, f1.y, acc.w);
        }
        float inv = s_inv[h2];
        float4 o;
        o.x = acc.x * inv; o.y = acc.y * inv; o.z = acc.z * inv; o.w = acc.w * inv;
        o.x = o.x > 0.f ? o.x : expm1f(o.x);
        o.y = o.y > 0.f ? o.y : expm1f(o.y);
        o.z = o.z > 0.f ? o.z : expm1f(o.z);
        o.w = o.w > 0.f ? o.w : expm1f(o.w);
        uint2 uo;
        *reinterpret_cast<__half2*>(&uo.x) = __floats2half2_rn(o.x, o.y);
        *reinterpret_cast<__half2*>(&uo.y) = __floats2half2_rn(o.z, o.w);
        *(uint2*)&g_x1h[(size_t)n * F1 + col] = uo;
    } else {
        __syncthreads();
        const int* sp = g_csr + beg;
        int h = tid >> 4;
        float erh = s_er[h];
        float m = -1e30f;
        for (int j = 0; j < deg; j++) {
            float x = g_el1[sp[j] * H0 + h] + erh;
            x = x > 0.f ? x : 0.2f * x;
            m = fmaxf(m, x);
        }
        float4 acc = make_float4(0.f, 0.f, 0.f, 0.f);
        float s = 0.f;
        const int col = tid * 4;
        for (int j = 0; j < deg; j++) {
            int si = sp[j];
            float x = g_el1[si * H0 + h] + erh;
            x = x > 0.f ? x : 0.2f * x;
            float w = __expf(x - m);
            s += w;
            uint2 u = *(const uint2*)&g_feat1h[(size_t)si * F1 + col];
            float2 f0 = __half22float2(*reinterpret_cast<__half2*>(&u.x));
            float2 f1 = __half22float2(*reinterpret_cast<__half2*>(&u.y));
            acc.x = fmaf(w, f0.x, acc.x);
            acc.y = fmaf(w, f0.y, acc.y);
            acc.z = fmaf(w, f1.x, acc.z);
            acc.w = fmaf(w, f1.y, acc.w);
        }
        float inv = 1.f / s;
        float4 o;
        o.x = acc.x * inv; o.y = acc.y * inv; o.z = acc.z * inv; o.w = acc.w * inv;
        o.x = o.x > 0.f ? o.x : expm1f(o.x);
        o.y = o.y > 0.f ? o.y : expm1f(o.y);
        o.z = o.z > 0.f ? o.z : expm1f(o.z);
        o.w = o.w > 0.f ? o.w : expm1f(o.w);
        uint2 uo;
        *reinterpret_cast<__half2*>(&uo.x) = __floats2half2_rn(o.x, o.y);
        *reinterpret_cast<__half2*>(&uo.y) = __floats2half2_rn(o.z, o.w);
        *(uint2*)&g_x1h[(size_t)n * F1 + col] = uo;
    }
}

// ================= fused per-node aggregation, layer 2 (writes d_out) =================
__global__ void __launch_bounds__(64)
node_agg2(float* __restrict__ out) {
    int n = blockIdx.x, tid = threadIdx.x;
    __shared__ int   s_src[MAXD];
    __shared__ float s_w[MAXD];
    __shared__ float s_red[2];
    int beg = g_off[n], deg = g_off[n + 1] - beg;
    float er = g_er2[n];

    if (deg <= MAXD) {
        for (int i = tid; i < deg; i += 64) s_src[i] = g_csr[beg + i];
        __syncthreads();
        float lmax = -1e30f;
        for (int j = tid; j < deg; j += 64) {
            float x = g_el2[s_src[j]] + er;
            x = x > 0.f ? x : 0.2f * x;
            s_w[j] = x;
            lmax = fmaxf(lmax, x);
        }
#pragma unroll
        for (int o = 16; o > 0; o >>= 1)
            lmax = fmaxf(lmax, __shfl_xor_sync(0xffffffffu, lmax, o));
        if ((tid & 31) == 0) s_red[tid >> 5] = lmax;
        __syncthreads();
        float m = fmaxf(s_red[0], s_red[1]);
        float lsum = 0.f;
        for (int j = tid; j < deg; j += 64) {
            float w = __expf(s_w[j] - m);
            s_w[j] = w;
            lsum += w;
        }
#pragma unroll
        for (int o = 16; o > 0; o >>= 1)
            lsum += __shfl_xor_sync(0xffffffffu, lsum, o);
        if ((tid & 31) == 0) s_red[tid >> 5] = lsum;
        __syncthreads();
        float s = s_red[0] + s_red[1];

        float acc = 0.f;
#pragma unroll 4
        for (int j = 0; j < deg; j++)
            acc = fmaf(s_w[j], __half2float(g_feat2h[(size_t)s_src[j] * OUT_D + tid]), acc);
        out[(size_t)n * OUT_D + tid] = (deg > 0) ? acc / s : 0.f;
    } else {
        __syncthreads();
        const int* sp = g_csr + beg;
        float m = -1e30f;
        for (int j = 0; j < deg; j++) {
            float x = g_el2[sp[j]] + er;
            x = x > 0.f ? x : 0.2f * x;
            m = fmaxf(m, x);
        }
        float acc = 0.f, s = 0.f;
        for (int j = 0; j < deg; j++) {
            int si = sp[j];
            float x = g_el2[si] + er;
            x = x > 0.f ? x : 0.2f * x;
            float w = __expf(x - m);
            s += w;
            acc = fmaf(w, __half2float(g_feat2h[(size_t)si * OUT_D + tid]), acc);
        }
        out[(size_t)n * OUT_D + tid] = acc / s;
    }
}

// ================= launch =================
extern "C" void kernel_launch(void* const* d_in, const int* in_sizes, int n_in,
                              void* d_out, int out_size) {
    (void)in_sizes; (void)n_in; (void)out_size;
    const float* h   = (const float*)d_in[0];
    const int*   src = (const int*)  d_in[1];
    const int*   dst = (const int*)  d_in[2];
    const float* W1  = (const float*)d_in[3];
    const float* al1 = (const float*)d_in[4];
    const float* ar1 = (const float*)d_in[5];
    const float* W2  = (const float*)d_in[6];
    const float* al2 = (const float*)d_in[7];
    const float* ar2 = (const float*)d_in[8];
    float* out = (float*)d_out;

    __half *p_feat1h, *p_x1h, *p_feat2h;
    float *p_el1, *p_er1, *p_el2, *p_er2;
    cudaGetSymbolAddress((void**)&p_feat1h, g_feat1h);
    cudaGetSymbolAddress((void**)&p_x1h,    g_x1h);
    cudaGetSymbolAddress((void**)&p_feat2h, g_feat2h);
    cudaGetSymbolAddress((void**)&p_el1,    g_el1);
    cudaGetSymbolAddress((void**)&p_er1,    g_er1);
    cudaGetSymbolAddress((void**)&p_el2,    g_el2);
    cudaGetSymbolAddress((void**)&p_er2,    g_er2);

    // ---- CSR build (shared by both layers) ----
    zero_deg<<<(N_NODES + 255) / 256, 256>>>();
    hist_kernel<<<(N_EDGES / 4 + 255) / 256, 256>>>((const int4*)dst);
    scan_kernel<<<1, 1024>>>();
    scatter_kernel<<<(N_EDGES / 4 + 255) / 256, 256>>>((const int4*)src, (const int4*)dst);

    // ---- layer 1 ----
    gemm_attn<float><<<dim3((N_NODES + 127) / 128, F1 / 64), 128>>>(
        h, W1, p_feat1h, N_NODES, F1, IN_DIM, al1, ar1, p_el1, p_er1, H0);
    node_agg1<<<N_NODES, 128>>>();

    // ---- layer 2 ----
    gemm_attn<__half><<<dim3((N_NODES + 127) / 128, OUT_D / 64), 128>>>(
        p_x1h, W2, p_feat2h, N_NODES, OUT_D, F1, al2, ar2, p_el2, p_er2, 1);
    node_agg2<<<N_NODES, 64>>>(out);
}

// round 14
// speedup vs baseline: 1.1049x; 1.0947x over previous
#include <cuda_runtime.h>
#include <cuda_fp16.h>
#include <math.h>

#define N_NODES 10000
#define N_EDGES 320000
#define IN_DIM  512
#define H0      8
#define D0      64
#define F1      512   /* H0*D0 */
#define OUT_D   64
#define MAXD    128   /* fast-path degree cap (smem); slow path beyond */

// ---------------- scratch (device globals; no allocation allowed) ----------------
__device__ __half g_feat1h[N_NODES * F1];   // h @ W1 (fp16)
__device__ __half g_x1h   [N_NODES * F1];   // layer-1 output (fp16)
__device__ __half g_feat2h[N_NODES * OUT_D];
__device__ float  g_el1  [N_NODES * H0];
__device__ float  g_er1  [N_NODES * H0];
__device__ float  g_el2  [N_NODES];
__device__ float  g_er2  [N_NODES];
__device__ int    g_deg  [N_NODES];
__device__ int    g_cur  [N_NODES];
__device__ int    g_off  [N_NODES + 1];
__device__ int    g_csr  [N_EDGES];         // src ids sorted by dst

// ================= CSR build =================
__global__ void zero_deg(void) {
    int i = blockIdx.x * blockDim.x + threadIdx.x;
    if (i < N_NODES) g_deg[i] = 0;
}

__global__ void hist_kernel(const int4* __restrict__ dst4) {
    int i = blockIdx.x * blockDim.x + threadIdx.x;
    if (i < N_EDGES / 4) {
        int4 d = dst4[i];
        atomicAdd(&g_deg[d.x], 1);
        atomicAdd(&g_deg[d.y], 1);
        atomicAdd(&g_deg[d.z], 1);
        atomicAdd(&g_deg[d.w], 1);
    }
}

__global__ void __launch_bounds__(1024) scan_kernel(void) {
    __shared__ int part[1024];
    int tid = threadIdx.x;
    int base = tid * 10;
    int sum = 0;
#pragma unroll
    for (int j = 0; j < 10; j++) {
        int idx = base + j;
        if (idx < N_NODES) sum += g_deg[idx];
    }
    part[tid] = sum;
    __syncthreads();
    for (int off = 1; off < 1024; off <<= 1) {
        int v = (tid >= off) ? part[tid - off] : 0;
        __syncthreads();
        part[tid] += v;
        __syncthreads();
    }
    int run = (tid > 0) ? part[tid - 1] : 0;
#pragma unroll
    for (int j = 0; j < 10; j++) {
        int idx = base + j;
        if (idx < N_NODES) {
            int v = g_deg[idx];
            g_off[idx] = run;
            g_cur[idx] = run;
            run += v;
        }
    }
    if (tid == 1023) g_off[N_NODES] = part[1023];
}

__global__ void scatter_kernel(const int4* __restrict__ src4, const int4* __restrict__ dst4) {
    int i = blockIdx.x * blockDim.x + threadIdx.x;
    if (i < N_EDGES / 4) {
        int4 s = src4[i];
        int4 d = dst4[i];
        int p0 = atomicAdd(&g_cur[d.x], 1);
        int p1 = atomicAdd(&g_cur[d.y], 1);
        int p2 = atomicAdd(&g_cur[d.z], 1);
        int p3 = atomicAdd(&g_cur[d.w], 1);
        g_csr[p0] = s.x; g_csr[p1] = s.y; g_csr[p2] = s.z; g_csr[p3] = s.w;
    }
}

// ================= tf32 GEMM + fused attention-logit epilogue =================
// C[M,N](fp16) = A[M,K] @ B[K,N];  BM=128, BN=64, BK=16; 128 thr = 4 warps (2x2).
// BN == head dim (64): block (m0, hh) holds head hh fully -> epilogue reduces
// el/er = feat . attn_{l,r}[hh] for its 128 rows and writes el_out/er_out.
__device__ __forceinline__ unsigned f2tf32(float f) {
    unsigned u;
    asm("cvt.rna.tf32.f32 %0, %1;" : "=r"(u) : "f"(f));
    return u;
}

template<typename AT>
__device__ __forceinline__ void load_tiles(
    const AT* __restrict__ A, const float* __restrict__ B,
    int M, int N, int K, int m0, int n0, int k0,
    int arow, int acol, int brow, int bcol, float4* pa, float4* pb)
{
#pragma unroll
    for (int j = 0; j < 4; j++) {
        int r = m0 + arow + j * 32;
        if (r < M) {
            if constexpr (sizeof(AT) == 4) {
                pa[j] = *(const float4*)&A[(size_t)r * K + k0 + acol];
            } else {
                uint2 u = *(const uint2*)&A[(size_t)r * K + k0 + acol];
                float2 f0 = __half22float2(*reinterpret_cast<__half2*>(&u.x));
                float2 f1 = __half22float2(*reinterpret_cast<__half2*>(&u.y));
                pa[j] = make_float4(f0.x, f0.y, f1.x, f1.y);
            }
        } else pa[j] = make_float4(0.f, 0.f, 0.f, 0.f);
    }
#pragma unroll
    for (int j = 0; j < 2; j++)
        pb[j] = *(const float4*)&B[(size_t)(k0 + brow) * N + n0 + bcol + j * 4];
}

template<typename AT>
__global__ void __launch_bounds__(128)
gemm_attn(const AT* __restrict__ A, const float* __restrict__ B,
          __half* __restrict__ C, int M, int N, int K,
          const float* __restrict__ al, const float* __restrict__ ar,
          float* __restrict__ el_out, float* __restrict__ er_out, int Hs)
{
    __shared__ unsigned As[2][128][20];
    __shared__ unsigned Bs[2][16][68];
    __shared__ float s_el[2][128], s_er[2][128];
    const int tid  = threadIdx.x;
    const int lane = tid & 31, warp = tid >> 5;
    const int wm = warp >> 1, wn = warp & 1;
    const int gid = lane >> 2, tig = lane & 3;
    const int m0 = blockIdx.x * 128, n0 = blockIdx.y * 64;
    const int hh = blockIdx.y;   // head index (BN == head dim)

    const int arow = tid >> 2;
    const int acol = (tid & 3) * 4;
    const int brow = tid >> 3;
    const int bcol = (tid & 7) * 8;

    float acc[4][4][4];
#pragma unroll
    for (int mi = 0; mi < 4; mi++)
#pragma unroll
        for (int ni = 0; ni < 4; ni++)
#pragma unroll
            for (int q = 0; q < 4; q++) acc[mi][ni][q] = 0.f;

    float4 pa[4], pb[2];
    load_tiles<AT>(A, B, M, N, K, m0, n0, 0, arow, acol, brow, bcol, pa, pb);
#pragma unroll
    for (int j = 0; j < 4; j++) {
        int r = arow + j * 32;
        As[0][r][acol + 0] = f2tf32(pa[j].x);
        As[0][r][acol + 1] = f2tf32(pa[j].y);
        As[0][r][acol + 2] = f2tf32(pa[j].z);
        As[0][r][acol + 3] = f2tf32(pa[j].w);
    }
#pragma unroll
    for (int j = 0; j < 2; j++) {
        Bs[0][brow][bcol + j * 4 + 0] = f2tf32(pb[j].x);
        Bs[0][brow][bcol + j * 4 + 1] = f2tf32(pb[j].y);
        Bs[0][brow][bcol + j * 4 + 2] = f2tf32(pb[j].z);
        Bs[0][brow][bcol + j * 4 + 3] = f2tf32(pb[j].w);
    }
    __syncthreads();

    int cur = 0;
    for (int k0 = 0; k0 < K; k0 += 16) {
        const bool more = (k0 + 16 < K);
        if (more)
            load_tiles<AT>(A, B, M, N, K, m0, n0, k0 + 16, arow, acol, brow, bcol, pa, pb);

#pragma unroll
        for (int kk = 0; kk < 2; kk++) {
            unsigned af[4][4], bf[4][2];
#pragma unroll
            for (int mi = 0; mi < 4; mi++) {
                int r = wm * 64 + mi * 16 + gid;
                af[mi][0] = As[cur][r    ][kk * 8 + tig];
                af[mi][1] = As[cur][r + 8][kk * 8 + tig];
                af[mi][2] = As[cur][r    ][kk * 8 + tig + 4];
                af[mi][3] = As[cur][r + 8][kk * 8 + tig + 4];
            }
#pragma unroll
            for (int ni = 0; ni < 4; ni++) {
                int c = wn * 32 + ni * 8 + gid;
                bf[ni][0] = Bs[cur][kk * 8 + tig    ][c];
                bf[ni][1] = Bs[cur][kk * 8 + tig + 4][c];
            }
#pragma unroll
            for (int mi = 0; mi < 4; mi++)
#pragma unroll
                for (int ni = 0; ni < 4; ni++) {
                    asm volatile(
                        "mma.sync.aligned.m16n8k8.row.col.f32.tf32.tf32.f32 "
                        "{%0,%1,%2,%3}, {%4,%5,%6,%7}, {%8,%9}, {%0,%1,%2,%3};"
                        : "+f"(acc[mi][ni][0]), "+f"(acc[mi][ni][1]),
                          "+f"(acc[mi][ni][2]), "+f"(acc[mi][ni][3])
                        : "r"(af[mi][0]), "r"(af[mi][1]), "r"(af[mi][2]), "r"(af[mi][3]),
                          "r"(bf[ni][0]), "r"(bf[ni][1]));
                }
        }

        if (more) {
            int nxt = cur ^ 1;
#pragma unroll
            for (int j = 0; j < 4; j++) {
                int r = arow + j * 32;
                As[nxt][r][acol + 0] = f2tf32(pa[j].x);
                As[nxt][r][acol + 1] = f2tf32(pa[j].y);
                As[nxt][r][acol + 2] = f2tf32(pa[j].z);
                As[nxt][r][acol + 3] = f2tf32(pa[j].w);
            }
#pragma unroll
            for (int j = 0; j < 2; j++) {
                Bs[nxt][brow][bcol + j * 4 + 0] = f2tf32(pb[j].x);
                Bs[nxt][brow][bcol + j * 4 + 1] = f2tf32(pb[j].y);
                Bs[nxt][brow][bcol + j * 4 + 2] = f2tf32(pb[j].z);
                Bs[nxt][brow][bcol + j * 4 + 3] = f2tf32(pb[j].w);
            }
            __syncthreads();
            cur = nxt;
        }
    }

    // ---- C store (fp16) ----
#pragma unroll
    for (int mi = 0; mi < 4; mi++)
#pragma unroll
        for (int ni = 0; ni < 4; ni++) {
            int r = m0 + wm * 64 + mi * 16 + gid;
            int c = n0 + wn * 32 + ni * 8 + 2 * tig;
            if (r < M)
                *(__half2*)&C[(size_t)r * N + c] =
                    __floats2half2_rn(acc[mi][ni][0], acc[mi][ni][1]);
            if (r + 8 < M)
                *(__half2*)&C[(size_t)(r + 8) * N + c] =
                    __floats2half2_rn(acc[mi][ni][2], acc[mi][ni][3]);
        }

    // ---- fused attention logits: el/er = feat . attn_{l,r}[hh] ----
#pragma unroll
    for (int mi = 0; mi < 4; mi++) {
        float el0 = 0.f, er0 = 0.f, el1 = 0.f, er1 = 0.f;
#pragma unroll
        for (int ni = 0; ni < 4; ni++) {
            int cl = wn * 32 + ni * 8 + 2 * tig;
            float A0 = al[hh * 64 + cl], A1 = al[hh * 64 + cl + 1];
            float R0 = ar[hh * 64 + cl], R1 = ar[hh * 64 + cl + 1];
            el0 = fmaf(acc[mi][ni][0], A0, fmaf(acc[mi][ni][1], A1, el0));
            er0 = fmaf(acc[mi][ni][0], R0, fmaf(acc[mi][ni][1], R1, er0));
            el1 = fmaf(acc[mi][ni][2], A0, fmaf(acc[mi][ni][3], A1, el1));
            er1 = fmaf(acc[mi][ni][2], R0, fmaf(acc[mi][ni][3], R1, er1));
        }
#pragma unroll
        for (int o = 1; o <= 2; o <<= 1) {
            el0 += __shfl_xor_sync(0xffffffffu, el0, o);
            er0 += __shfl_xor_sync(0xffffffffu, er0, o);
            el1 += __shfl_xor_sync(0xffffffffu, el1, o);
            er1 += __shfl_xor_sync(0xffffffffu, er1, o);
        }
        if (tig == 0) {
            int r = wm * 64 + mi * 16 + gid;
            s_el[wn][r]     = el0;  s_er[wn][r]     = er0;
            s_el[wn][r + 8] = el1;  s_er[wn][r + 8] = er1;
        }
    }
    __syncthreads();
    {
        int r = tid;
        if (m0 + r < M) {
            el_out[(size_t)(m0 + r) * Hs + hh] = s_el[0][r] + s_el[1][r];
            er_out[(size_t)(m0 + r) * Hs + hh] = s_er[0][r] + s_er[1][r];
        }
    }
}

// ================= fused per-node aggregation, layer 1 =================
__global__ void __launch_bounds__(128)
node_agg1(void) {
    int n   = blockIdx.x;
    int tid = threadIdx.x;
    __shared__ int   s_src[MAXD];
    __shared__ float s_w[MAXD][H0];
    __shared__ float s_red[16][H0];
    __shared__ float s_mh[H0], s_inv[H0], s_er[H0];
    int beg = g_off[n], deg = g_off[n + 1] - beg;
    if (tid < 8) s_er[tid] = g_er1[n * H0 + tid];

    if (deg <= MAXD) {
        if (tid < deg) s_src[tid] = g_csr[beg + tid];
        __syncthreads();
        int h = tid & 7, r = tid >> 3;   // r in 0..15
        float lmax = -1e30f;
        for (int j = r; j < deg; j += 16) {
            float x = g_el1[s_src[j] * H0 + h] + s_er[h];
            x = x > 0.f ? x : 0.2f * x;
            s_w[j][h] = x;
            lmax = fmaxf(lmax, x);
        }
        s_red[r][h] = lmax;
        __syncthreads();
        if (tid < 8) {
            float m = s_red[0][tid];
#pragma unroll
            for (int q = 1; q < 16; q++) m = fmaxf(m, s_red[q][tid]);
            s_mh[tid] = m;
        }
        __syncthreads();
        float mh = s_mh[h];
        float lsum = 0.f;
        for (int j = r; j < deg; j += 16) {
            float w = __expf(s_w[j][h] - mh);
            s_w[j][h] = w;
            lsum += w;
        }
        s_red[r][h] = lsum;
        __syncthreads();
        if (tid < 8) {
            float s = 0.f;
#pragma unroll
            for (int q = 0; q < 16; q++) s += s_red[q][tid];
            s_inv[tid] = (deg > 0) ? 1.f / s : 0.f;
        }
        __syncthreads();

        int h2 = tid >> 4;
        const int col = tid * 4;
        float4 acc = make_float4(0.f, 0.f, 0.f, 0.f);
#pragma unroll 4
        for (int j = 0; j < deg; j++) {
            float w = s_w[j][h2];
            uint2 u = *(const uint2*)&g_feat1h[(size_t)s_src[j] * F1 + col];
            float2 f0 = __half22float2(*reinterpret_cast<__half2*>(&u.x));
            float2 f1 = __half22float2(*reinterpret_cast<__half2*>(&u.y));
            acc.x = fmaf(w, f0.x, acc.x);
            acc.y = fmaf(w, f0.y, acc.y);
            acc.z = fmaf(w, f1.x, acc.z);
            acc.w = fmaf(w, f1.y, acc.w);
        }
        float inv = s_inv[h2];
        float4 o;
        o.x = acc.x * inv; o.y = acc.y * inv; o.z = acc.z * inv; o.w = acc.w * inv;
        o.x = o.x > 0.f ? o.x : expm1f(o.x);
        o.y = o.y > 0.f ? o.y : expm1f(o.y);
        o.z = o.z > 0.f ? o.z : expm1f(o.z);
        o.w = o.w > 0.f ? o.w : expm1f(o.w);
        uint2 uo;
        *reinterpret_cast<__half2*>(&uo.x) = __floats2half2_rn(o.x, o.y);
        *reinterpret_cast<__half2*>(&uo.y) = __floats2half2_rn(o.z, o.w);
        *(uint2*)&g_x1h[(size_t)n * F1 + col] = uo;
    } else {
        __syncthreads();
        const int* sp = g_csr + beg;
        int h = tid >> 4;
        float erh = s_er[h];
        float m = -1e30f;
        for (int j = 0; j < deg; j++) {
            float x = g_el1[sp[j] * H0 + h] + erh;
            x = x > 0.f ? x : 0.2f * x;
            m = fmaxf(m, x);
        }
        float4 acc = make_float4(0.f, 0.f, 0.f, 0.f);
        float s = 0.f;
        const int col = tid * 4;
        for (int j = 0; j < deg; j++) {
            int si = sp[j];
            float x = g_el1[si * H0 + h] + erh;
            x = x > 0.f ? x : 0.2f * x;
            float w = __expf(x - m);
            s += w;
            uint2 u = *(const uint2*)&g_feat1h[(size_t)si * F1 + col];
            float2 f0 = __half22float2(*reinterpret_cast<__half2*>(&u.x));
            float2 f1 = __half22float2(*reinterpret_cast<__half2*>(&u.y));
            acc.x = fmaf(w, f0.x, acc.x);
            acc.y = fmaf(w, f0.y, acc.y);
            acc.z = fmaf(w, f1.x, acc.z);
            acc.w = fmaf(w, f1.y, acc.w);
        }
        float inv = 1.f / s;
        float4 o;
        o.x = acc.x * inv; o.y = acc.y * inv; o.z = acc.z * inv; o.w = acc.w * inv;
        o.x = o.x > 0.f ? o.x : expm1f(o.x);
        o.y = o.y > 0.f ? o.y : expm1f(o.y);
        o.z = o.z > 0.f ? o.z : expm1f(o.z);
        o.w = o.w > 0.f ? o.w : expm1f(o.w);
        uint2 uo;
        *reinterpret_cast<__half2*>(&uo.x) = __floats2half2_rn(o.x, o.y);
        *reinterpret_cast<__half2*>(&uo.y) = __floats2half2_rn(o.z, o.w);
        *(uint2*)&g_x1h[(size_t)n * F1 + col] = uo;
    }
}

// ================= fused per-node aggregation, layer 2 (writes d_out) =================
__global__ void __launch_bounds__(64)
node_agg2(float* __restrict__ out) {
    int n = blockIdx.x, tid = threadIdx.x;
    __shared__ int   s_src[MAXD];
    __shared__ float s_w[MAXD];
    __shared__ float s_red[2];
    int beg = g_off[n], deg = g_off[n + 1] - beg;
    float er = g_er2[n];

    if (deg <= MAXD) {
        for (int i = tid; i < deg; i += 64) s_src[i] = g_csr[beg + i];
        __syncthreads();
        float lmax = -1e30f;
        for (int j = tid; j < deg; j += 64) {
            float x = g_el2[s_src[j]] + er;
            x = x > 0.f ? x : 0.2f * x;
            s_w[j] = x;
            lmax = fmaxf(lmax, x);
        }
#pragma unroll
        for (int o = 16; o > 0; o >>= 1)
            lmax = fmaxf(lmax, __shfl_xor_sync(0xffffffffu, lmax, o));
        if ((tid & 31) == 0) s_red[tid >> 5] = lmax;
        __syncthreads();
        float m = fmaxf(s_red[0], s_red[1]);
        float lsum = 0.f;
        for (int j = tid; j < deg; j += 64) {
            float w = __expf(s_w[j] - m);
            s_w[j] = w;
            lsum += w;
        }
#pragma unroll
        for (int o = 16; o > 0; o >>= 1)
            lsum += __shfl_xor_sync(0xffffffffu, lsum, o);
        if ((tid & 31) == 0) s_red[tid >> 5] = lsum;
        __syncthreads();
        float s = s_red[0] + s_red[1];

        float acc = 0.f;
#pragma unroll 4
        for (int j = 0; j < deg; j++)
            acc = fmaf(s_w[j], __half2float(g_feat2h[(size_t)s_src[j] * OUT_D + tid]), acc);
        out[(size_t)n * OUT_D + tid] = (deg > 0) ? acc / s : 0.f;
    } else {
        __syncthreads();
        const int* sp = g_csr + beg;
        float m = -1e30f;
        for (int j = 0; j < deg; j++) {
            float x = g_el2[sp[j]] + er;
            x = x > 0.f ? x : 0.2f * x;
            m = fmaxf(m, x);
        }
        float acc = 0.f, s = 0.f;
        for (int j = 0; j < deg; j++) {
            int si = sp[j];
            float x = g_el2[si] + er;
            x = x > 0.f ? x : 0.2f * x;
            float w = __expf(x - m);
            s += w;
            acc = fmaf(w, __half2float(g_feat2h[(size_t)si * OUT_D + tid]), acc);
        }
        out[(size_t)n * OUT_D + tid] = acc / s;
    }
}

// ================= launch =================
extern "C" void kernel_launch(void* const* d_in, const int* in_sizes, int n_in,
                              void* d_out, int out_size) {
    (void)in_sizes; (void)n_in; (void)out_size;
    const float* h   = (const float*)d_in[0];
    const int*   src = (const int*)  d_in[1];
    const int*   dst = (const int*)  d_in[2];
    const float* W1  = (const float*)d_in[3];
    const float* al1 = (const float*)d_in[4];
    const float* ar1 = (const float*)d_in[5];
    const float* W2  = (const float*)d_in[6];
    const float* al2 = (const float*)d_in[7];
    const float* ar2 = (const float*)d_in[8];
    float* out = (float*)d_out;

    __half *p_feat1h, *p_x1h, *p_feat2h;
    float *p_el1, *p_er1, *p_el2, *p_er2;
    cudaGetSymbolAddress((void**)&p_feat1h, g_feat1h);
    cudaGetSymbolAddress((void**)&p_x1h,    g_x1h);
    cudaGetSymbolAddress((void**)&p_feat2h, g_feat2h);
    cudaGetSymbolAddress((void**)&p_el1,    g_el1);
    cudaGetSymbolAddress((void**)&p_er1,    g_er1);
    cudaGetSymbolAddress((void**)&p_el2,    g_el2);
    cudaGetSymbolAddress((void**)&p_er2,    g_er2);

    // One-time host-side resources for forked capture (no device memory).
    static cudaStream_t s_csr = 0;
    static cudaEvent_t  e_fork = 0, e_join = 0;
    if (s_csr == 0) {
        cudaStreamCreateWithFlags(&s_csr, cudaStreamNonBlocking);
        cudaEventCreateWithFlags(&e_fork, cudaEventDisableTiming);
        cudaEventCreateWithFlags(&e_join, cudaEventDisableTiming);
    }

    // ---- fork: CSR build on side stream, concurrent with GEMM1 ----
    cudaEventRecord(e_fork, 0);
    cudaStreamWaitEvent(s_csr, e_fork, 0);
    zero_deg<<<(N_NODES + 255) / 256, 256, 0, s_csr>>>();
    hist_kernel<<<(N_EDGES / 4 + 255) / 256, 256, 0, s_csr>>>((const int4*)dst);
    scan_kernel<<<1, 1024, 0, s_csr>>>();
    scatter_kernel<<<(N_EDGES / 4 + 255) / 256, 256, 0, s_csr>>>((const int4*)src,
                                                                 (const int4*)dst);
    cudaEventRecord(e_join, s_csr);

    // ---- main stream: GEMM1 (independent of CSR) ----
    gemm_attn<float><<<dim3((N_NODES + 127) / 128, F1 / 64), 128>>>(
        h, W1, p_feat1h, N_NODES, F1, IN_DIM, al1, ar1, p_el1, p_er1, H0);

    // ---- join: aggregation needs both GEMM1 and CSR ----
    cudaStreamWaitEvent(0, e_join, 0);
    node_agg1<<<N_NODES, 128>>>();

    // ---- layer 2 ----
    gemm_attn<__half><<<dim3((N_NODES + 127) / 128, OUT_D / 64), 128>>>(
        p_x1h, W2, p_feat2h, N_NODES, OUT_D, F1, al2, ar2, p_el2, p_er2, 1);
    node_agg2<<<N_NODES, 64>>>(out);
}

// round 15
// speedup vs baseline: 1.2369x; 1.1194x over previous
#include <cuda_runtime.h>
#include <cuda_fp16.h>
#include <math.h>

#define N_NODES 10000
#define N_EDGES 320000
#define IN_DIM  512
#define H0      8
#define D0      64
#define F1      512   /* H0*D0 */
#define OUT_D   64
#define MAXD    128   /* fast-path degree cap (smem); slow path beyond */

// ---------------- scratch (device globals; no allocation allowed) ----------------
__device__ __half g_feat1h[N_NODES * F1];   // h @ W1 (fp16)
__device__ __half g_x1h   [N_NODES * F1];   // layer-1 output (fp16)
__device__ __half g_feat2h[N_NODES * OUT_D];
__device__ float  g_el1  [N_NODES * H0];
__device__ float  g_er1  [N_NODES * H0];
__device__ float  g_el2  [N_NODES];
__device__ float  g_er2  [N_NODES];
__device__ int    g_deg  [N_NODES];
__device__ int    g_cur  [N_NODES];
__device__ int    g_off  [N_NODES + 1];
__device__ int    g_csr  [N_EDGES];         // src ids sorted by dst

// ================= CSR build =================
__global__ void zero_deg(void) {
    int i = blockIdx.x * blockDim.x + threadIdx.x;
    if (i < N_NODES) g_deg[i] = 0;
}

__global__ void hist_kernel(const int4* __restrict__ dst4) {
    int i = blockIdx.x * blockDim.x + threadIdx.x;
    if (i < N_EDGES / 4) {
        int4 d = dst4[i];
        atomicAdd(&g_deg[d.x], 1);
        atomicAdd(&g_deg[d.y], 1);
        atomicAdd(&g_deg[d.z], 1);
        atomicAdd(&g_deg[d.w], 1);
    }
}

__global__ void __launch_bounds__(1024) scan_kernel(void) {
    __shared__ int part[1024];
    int tid = threadIdx.x;
    int base = tid * 10;
    int sum = 0;
#pragma unroll
    for (int j = 0; j < 10; j++) {
        int idx = base + j;
        if (idx < N_NODES) sum += g_deg[idx];
    }
    part[tid] = sum;
    __syncthreads();
    for (int off = 1; off < 1024; off <<= 1) {
        int v = (tid >= off) ? part[tid - off] : 0;
        __syncthreads();
        part[tid] += v;
        __syncthreads();
    }
    int run = (tid > 0) ? part[tid - 1] : 0;
#pragma unroll
    for (int j = 0; j < 10; j++) {
        int idx = base + j;
        if (idx < N_NODES) {
            int v = g_deg[idx];
            g_off[idx] = run;
            g_cur[idx] = run;
            run += v;
        }
    }
    if (tid == 1023) g_off[N_NODES] = part[1023];
}

__global__ void scatter_kernel(const int4* __restrict__ src4, const int4* __restrict__ dst4) {
    int i = blockIdx.x * blockDim.x + threadIdx.x;
    if (i < N_EDGES / 4) {
        int4 s = src4[i];
        int4 d = dst4[i];
        int p0 = atomicAdd(&g_cur[d.x], 1);
        int p1 = atomicAdd(&g_cur[d.y], 1);
        int p2 = atomicAdd(&g_cur[d.z], 1);
        int p3 = atomicAdd(&g_cur[d.w], 1);
        g_csr[p0] = s.x; g_csr[p1] = s.y; g_csr[p2] = s.z; g_csr[p3] = s.w;
    }
}

// ================= fp16 tensor-core GEMM + fused attention-logit epilogue =====
// C[M,N](fp16) = A[M,K] @ B[K,N];  BM=128, BN=64, BK=16; 128 thr = 4 warps (2x2).
// mma.sync.m16n8k16.f16 with fp32 accumulate (fp16 mantissa == tf32 mantissa).
// BN == head dim (64): block (m0, hh) holds head hh fully -> epilogue reduces
// el/er = feat . attn_{l,r}[hh] for its 128 rows.

template<typename AT>
__device__ __forceinline__ void load_tiles(
    const AT* __restrict__ A, const float* __restrict__ B,
    int M, int N, int K, int m0, int n0, int k0,
    int arow, int acol, int brow, int bcol, uint2* pa, float4* pb)
{
#pragma unroll
    for (int j = 0; j < 4; j++) {
        int r = m0 + arow + j * 32;
        if (r < M) {
            if constexpr (sizeof(AT) == 4) {
                float4 v = *(const float4*)&A[(size_t)r * K + k0 + acol];
                __half2 h0 = __floats2half2_rn(v.x, v.y);
                __half2 h1 = __floats2half2_rn(v.z, v.w);
                pa[j].x = *reinterpret_cast<unsigned*>(&h0);
                pa[j].y = *reinterpret_cast<unsigned*>(&h1);
            } else {
                pa[j] = *(const uint2*)&A[(size_t)r * K + k0 + acol];
            }
        } else pa[j] = make_uint2(0u, 0u);
    }
#pragma unroll
    for (int j = 0; j < 2; j++)
        pb[j] = *(const float4*)&B[(size_t)(k0 + brow) * N + n0 + bcol + j * 4];
}

template<typename AT>
__global__ void __launch_bounds__(128)
gemm_attn(const AT* __restrict__ A, const float* __restrict__ B,
          __half* __restrict__ C, int M, int N, int K,
          const float* __restrict__ al, const float* __restrict__ ar,
          float* __restrict__ el_out, float* __restrict__ er_out, int Hs)
{
    // As: half2 words, [m][k2] (k2 = k/2, 8 words + 1 pad)
    // Bs: halfs, [n][k] (16 + 2 pad) -> b-fragments load as half2 along k
    __shared__ unsigned As[2][128][9];
    __shared__ __half   Bs[2][64][18];
    __shared__ float s_el[2][128], s_er[2][128];
    const int tid  = threadIdx.x;
    const int lane = tid & 31, warp = tid >> 5;
    const int wm = warp >> 1, wn = warp & 1;
    const int gid = lane >> 2, tig = lane & 3;
    const int m0 = blockIdx.x * 128, n0 = blockIdx.y * 64;
    const int hh = blockIdx.y;   // head index (BN == head dim)

    const int arow = tid >> 2;           // 0..31 (+j*32)
    const int acol = (tid & 3) * 4;      // k offset (elements)
    const int ac2  = (tid & 3) * 2;      // k offset (half2 words)
    const int brow = tid >> 3;           // 0..15  (k index)
    const int bcol = (tid & 7) * 8;      // 0..56  (n offset)

    float acc[4][4][4];
#pragma unroll
    for (int mi = 0; mi < 4; mi++)
#pragma unroll
        for (int ni = 0; ni < 4; ni++)
#pragma unroll
            for (int q = 0; q < 4; q++) acc[mi][ni][q] = 0.f;

    uint2 pa[4]; float4 pb[2];
    load_tiles<AT>(A, B, M, N, K, m0, n0, 0, arow, acol, brow, bcol, pa, pb);
#pragma unroll
    for (int j = 0; j < 4; j++) {
        int r = arow + j * 32;
        As[0][r][ac2 + 0] = pa[j].x;
        As[0][r][ac2 + 1] = pa[j].y;
    }
#pragma unroll
    for (int j = 0; j < 2; j++) {
        Bs[0][bcol + j * 4 + 0][brow] = __float2half(pb[j].x);
        Bs[0][bcol + j * 4 + 1][brow] = __float2half(pb[j].y);
        Bs[0][bcol + j * 4 + 2][brow] = __float2half(pb[j].z);
        Bs[0][bcol + j * 4 + 3][brow] = __float2half(pb[j].w);
    }
    __syncthreads();

    int cur = 0;
    for (int k0 = 0; k0 < K; k0 += 16) {
        const bool more = (k0 + 16 < K);
        if (more)
            load_tiles<AT>(A, B, M, N, K, m0, n0, k0 + 16, arow, acol, brow, bcol, pa, pb);

        unsigned af[4][4], bf[4][2];
#pragma unroll
        for (int mi = 0; mi < 4; mi++) {
            int r = wm * 64 + mi * 16 + gid;
            af[mi][0] = As[cur][r    ][tig];
            af[mi][1] = As[cur][r + 8][tig];
            af[mi][2] = As[cur][r    ][tig + 4];
            af[mi][3] = As[cur][r + 8][tig + 4];
        }
#pragma unroll
        for (int ni = 0; ni < 4; ni++) {
            int c = wn * 32 + ni * 8 + gid;
            bf[ni][0] = *(const unsigned*)&Bs[cur][c][2 * tig];
            bf[ni][1] = *(const unsigned*)&Bs[cur][c][2 * tig + 8];
        }
#pragma unroll
        for (int mi = 0; mi < 4; mi++)
#pragma unroll
            for (int ni = 0; ni < 4; ni++) {
                asm volatile(
                    "mma.sync.aligned.m16n8k16.row.col.f32.f16.f16.f32 "
                    "{%0,%1,%2,%3}, {%4,%5,%6,%7}, {%8,%9}, {%0,%1,%2,%3};"
                    : "+f"(acc[mi][ni][0]), "+f"(acc[mi][ni][1]),
                      "+f"(acc[mi][ni][2]), "+f"(acc[mi][ni][3])
                    : "r"(af[mi][0]), "r"(af[mi][1]), "r"(af[mi][2]), "r"(af[mi][3]),
                      "r"(bf[ni][0]), "r"(bf[ni][1]));
            }

        if (more) {
            int nxt = cur ^ 1;
#pragma unroll
            for (int j = 0; j < 4; j++) {
                int r = arow + j * 32;
                As[nxt][r][ac2 + 0] = pa[j].x;
                As[nxt][r][ac2 + 1] = pa[j].y;
            }
#pragma unroll
            for (int j = 0; j < 2; j++) {
                Bs[nxt][bcol + j * 4 + 0][brow] = __float2half(pb[j].x);
                Bs[nxt][bcol + j * 4 + 1][brow] = __float2half(pb[j].y);
                Bs[nxt][bcol + j * 4 + 2][brow] = __float2half(pb[j].z);
                Bs[nxt][bcol + j * 4 + 3][brow] = __float2half(pb[j].w);
            }
            __syncthreads();
            cur = nxt;
        }
    }

    // ---- C store (fp16) ----
#pragma unroll
    for (int mi = 0; mi < 4; mi++)
#pragma unroll
        for (int ni = 0; ni < 4; ni++) {
            int r = m0 + wm * 64 + mi * 16 + gid;
            int c = n0 + wn * 32 + ni * 8 + 2 * tig;
            if (r < M)
                *(__half2*)&C[(size_t)r * N + c] =
                    __floats2half2_rn(acc[mi][ni][0], acc[mi][ni][1]);
            if (r + 8 < M)
                *(__half2*)&C[(size_t)(r + 8) * N + c] =
                    __floats2half2_rn(acc[mi][ni][2], acc[mi][ni][3]);
        }

    // ---- fused attention logits: el/er = feat . attn_{l,r}[hh] ----
#pragma unroll
    for (int mi = 0; mi < 4; mi++) {
        float el0 = 0.f, er0 = 0.f, el1 = 0.f, er1 = 0.f;
#pragma unroll
        for (int ni = 0; ni < 4; ni++) {
            int cl = wn * 32 + ni * 8 + 2 * tig;
            float A0 = al[hh * 64 + cl], A1 = al[hh * 64 + cl + 1];
            float R0 = ar[hh * 64 + cl], R1 = ar[hh * 64 + cl + 1];
            el0 = fmaf(acc[mi][ni][0], A0, fmaf(acc[mi][ni][1], A1, el0));
            er0 = fmaf(acc[mi][ni][0], R0, fmaf(acc[mi][ni][1], R1, er0));
            el1 = fmaf(acc[mi][ni][2], A0, fmaf(acc[mi][ni][3], A1, el1));
            er1 = fmaf(acc[mi][ni][2], R0, fmaf(acc[mi][ni][3], R1, er1));
        }
#pragma unroll
        for (int o = 1; o <= 2; o <<= 1) {
            el0 += __shfl_xor_sync(0xffffffffu, el0, o);
            er0 += __shfl_xor_sync(0xffffffffu, er0, o);
            el1 += __shfl_xor_sync(0xffffffffu, el1, o);
            er1 += __shfl_xor_sync(0xffffffffu, er1, o);
        }
        if (tig == 0) {
            int r = wm * 64 + mi * 16 + gid;
            s_el[wn][r]     = el0;  s_er[wn][r]     = er0;
            s_el[wn][r + 8] = el1;  s_er[wn][r + 8] = er1;
        }
    }
    __syncthreads();
    {
        int r = tid;
        if (m0 + r < M) {
            el_out[(size_t)(m0 + r) * Hs + hh] = s_el[0][r] + s_el[1][r];
            er_out[(size_t)(m0 + r) * Hs + hh] = s_er[0][r] + s_er[1][r];
        }
    }
}

// ================= fused per-node aggregation, layer 1 =================
__global__ void __launch_bounds__(128)
node_agg1(void) {
    int n   = blockIdx.x;
    int tid = threadIdx.x;
    __shared__ int   s_src[MAXD];
    __shared__ float s_w[MAXD][H0];
    __shared__ float s_red[16][H0];
    __shared__ float s_mh[H0], s_inv[H0], s_er[H0];
    int beg = g_off[n], deg = g_off[n + 1] - beg;
    if (tid < 8) s_er[tid] = g_er1[n * H0 + tid];

    if (deg <= MAXD) {
        if (tid < deg) s_src[tid] = g_csr[beg + tid];
        __syncthreads();
        int h = tid & 7, r = tid >> 3;   // r in 0..15
        float lmax = -1e30f;
        for (int j = r; j < deg; j += 16) {
            float x = g_el1[s_src[j] * H0 + h] + s_er[h];
            x = x > 0.f ? x : 0.2f * x;
            s_w[j][h] = x;
            lmax = fmaxf(lmax, x);
        }
        s_red[r][h] = lmax;
        __syncthreads();
        if (tid < 8) {
            float m = s_red[0][tid];
#pragma unroll
            for (int q = 1; q < 16; q++) m = fmaxf(m, s_red[q][tid]);
            s_mh[tid] = m;
        }
        __syncthreads();
        float mh = s_mh[h];
        float lsum = 0.f;
        for (int j = r; j < deg; j += 16) {
            float w = __expf(s_w[j][h] - mh);
            s_w[j][h] = w;
            lsum += w;
        }
        s_red[r][h] = lsum;
        __syncthreads();
        if (tid < 8) {
            float s = 0.f;
#pragma unroll
            for (int q = 0; q < 16; q++) s += s_red[q][tid];
            s_inv[tid] = (deg > 0) ? 1.f / s : 0.f;
        }
        __syncthreads();

        int h2 = tid >> 4;
        const int col = tid * 4;
        float4 acc = make_float4(0.f, 0.f, 0.f, 0.f);
#pragma unroll 4
        for (int j = 0; j < deg; j++) {
            float w = s_w[j][h2];
            uint2 u = *(const uint2*)&g_feat1h[(size_t)s_src[j] * F1 + col];
            float2 f0 = __half22float2(*reinterpret_cast<__half2*>(&u.x));
            float2 f1 = __half22float2(*reinterpret_cast<__half2*>(&u.y));
            acc.x = fmaf(w, f0.x, acc.x);
            acc.y = fmaf(w, f0.y, acc.y);
            acc.z = fmaf(w, f1.x, acc.z);
            acc.w = fmaf(w, f1.y, acc.w);
        }
        float inv = s_inv[h2];
        float4 o;
        o.x = acc.x * inv; o.y = acc.y * inv; o.z = acc.z * inv; o.w = acc.w * inv;
        o.x = o.x > 0.f ? o.x : expm1f(o.x);
        o.y = o.y > 0.f ? o.y : expm1f(o.y);
        o.z = o.z > 0.f ? o.z : expm1f(o.z);
        o.w = o.w > 0.f ? o.w : expm1f(o.w);
        uint2 uo;
        *reinterpret_cast<__half2*>(&uo.x) = __floats2half2_rn(o.x, o.y);
        *reinterpret_cast<__half2*>(&uo.y) = __floats2half2_rn(o.z, o.w);
        *(uint2*)&g_x1h[(size_t)n * F1 + col] = uo;
    } else {
        __syncthreads();
        const int* sp = g_csr + beg;
        int h = tid >> 4;
        float erh = s_er[h];
        float m = -1e30f;
        for (int j = 0; j < deg; j++) {
            float x = g_el1[sp[j] * H0 + h] + erh;
            x = x > 0.f ? x : 0.2f * x;
            m = fmaxf(m, x);
        }
        float4 acc = make_float4(0.f, 0.f, 0.f, 0.f);
        float s = 0.f;
        const int col = tid * 4;
        for (int j = 0; j < deg; j++) {
            int si = sp[j];
            float x = g_el1[si * H0 + h] + erh;
            x = x > 0.f ? x : 0.2f * x;
            float w = __expf(x - m);
            s += w;
            uint2 u = *(const uint2*)&g_feat1h[(size_t)si * F1 + col];
            float2 f0 = __half22float2(*reinterpret_cast<__half2*>(&u.x));
            float2 f1 = __half22float2(*reinterpret_cast<__half2*>(&u.y));
            acc.x = fmaf(w, f0.x, acc.x);
            acc.y = fmaf(w, f0.y, acc.y);
            acc.z = fmaf(w, f1.x, acc.z);
            acc.w = fmaf(w, f1.y, acc.w);
        }
        float inv = 1.f / s;
        float4 o;
        o.x = acc.x * inv; o.y = acc.y * inv; o.z = acc.z * inv; o.w = acc.w * inv;
        o.x = o.x > 0.f ? o.x : expm1f(o.x);
        o.y = o.y > 0.f ? o.y : expm1f(o.y);
        o.z = o.z > 0.f ? o.z : expm1f(o.z);
        o.w = o.w > 0.f ? o.w : expm1f(o.w);
        uint2 uo;
        *reinterpret_cast<__half2*>(&uo.x) = __floats2half2_rn(o.x, o.y);
        *reinterpret_cast<__half2*>(&uo.y) = __floats2half2_rn(o.z, o.w);
        *(uint2*)&g_x1h[(size_t)n * F1 + col] = uo;
    }
}

// ================= fused per-node aggregation, layer 2 (writes d_out) =================
__global__ void __launch_bounds__(64)
node_agg2(float* __restrict__ out) {
    int n = blockIdx.x, tid = threadIdx.x;
    __shared__ int   s_src[MAXD];
    __shared__ float s_w[MAXD];
    __shared__ float s_red[2];
    int beg = g_off[n], deg = g_off[n + 1] - beg;
    float er = g_er2[n];

    if (deg <= MAXD) {
        for (int i = tid; i < deg; i += 64) s_src[i] = g_csr[beg + i];
        __syncthreads();
        float lmax = -1e30f;
        for (int j = tid; j < deg; j += 64) {
            float x = g_el2[s_src[j]] + er;
            x = x > 0.f ? x : 0.2f * x;
            s_w[j] = x;
            lmax = fmaxf(lmax, x);
        }
#pragma unroll
        for (int o = 16; o > 0; o >>= 1)
            lmax = fmaxf(lmax, __shfl_xor_sync(0xffffffffu, lmax, o));
        if ((tid & 31) == 0) s_red[tid >> 5] = lmax;
        __syncthreads();
        float m = fmaxf(s_red[0], s_red[1]);
        float lsum = 0.f;
        for (int j = tid; j < deg; j += 64) {
            float w = __expf(s_w[j] - m);
            s_w[j] = w;
            lsum += w;
        }
#pragma unroll
        for (int o = 16; o > 0; o >>= 1)
            lsum += __shfl_xor_sync(0xffffffffu, lsum, o);
        if ((tid & 31) == 0) s_red[tid >> 5] = lsum;
        __syncthreads();
        float s = s_red[0] + s_red[1];

        float acc = 0.f;
#pragma unroll 4
        for (int j = 0; j < deg; j++)
            acc = fmaf(s_w[j], __half2float(g_feat2h[(size_t)s_src[j] * OUT_D + tid]), acc);
        out[(size_t)n * OUT_D + tid] = (deg > 0) ? acc / s : 0.f;
    } else {
        __syncthreads();
        const int* sp = g_csr + beg;
        float m = -1e30f;
        for (int j = 0; j < deg; j++) {
            float x = g_el2[sp[j]] + er;
            x = x > 0.f ? x : 0.2f * x;
            m = fmaxf(m, x);
        }
        float acc = 0.f, s = 0.f;
        for (int j = 0; j < deg; j++) {
            int si = sp[j];
            float x = g_el2[si] + er;
            x = x > 0.f ? x : 0.2f * x;
            float w = __expf(x - m);
            s += w;
            acc = fmaf(w, __half2float(g_feat2h[(size_t)si * OUT_D + tid]), acc);
        }
        out[(size_t)n * OUT_D + tid] = acc / s;
    }
}

// ================= launch =================
extern "C" void kernel_launch(void* const* d_in, const int* in_sizes, int n_in,
                              void* d_out, int out_size) {
    (void)in_sizes; (void)n_in; (void)out_size;
    const float* h   = (const float*)d_in[0];
    const int*   src = (const int*)  d_in[1];
    const int*   dst = (const int*)  d_in[2];
    const float* W1  = (const float*)d_in[3];
    const float* al1 = (const float*)d_in[4];
    const float* ar1 = (const float*)d_in[5];
    const float* W2  = (const float*)d_in[6];
    const float* al2 = (const float*)d_in[7];
    const float* ar2 = (const float*)d_in[8];
    float* out = (float*)d_out;

    __half *p_feat1h, *p_x1h, *p_feat2h;
    float *p_el1, *p_er1, *p_el2, *p_er2;
    cudaGetSymbolAddress((void**)&p_feat1h, g_feat1h);
    cudaGetSymbolAddress((void**)&p_x1h,    g_x1h);
    cudaGetSymbolAddress((void**)&p_feat2h, g_feat2h);
    cudaGetSymbolAddress((void**)&p_el1,    g_el1);
    cudaGetSymbolAddress((void**)&p_er1,    g_er1);
    cudaGetSymbolAddress((void**)&p_el2,    g_el2);
    cudaGetSymbolAddress((void**)&p_er2,    g_er2);

    // One-time host-side resources for forked capture (no device memory).
    static cudaStream_t s_csr = 0;
    static cudaEvent_t  e_fork = 0, e_join = 0;
    if (s_csr == 0) {
        cudaStreamCreateWithFlags(&s_csr, cudaStreamNonBlocking);
        cudaEventCreateWithFlags(&e_fork, cudaEventDisableTiming);
        cudaEventCreateWithFlags(&e_join, cudaEventDisableTiming);
    }

    // ---- fork: CSR build on side stream, concurrent with GEMM1 ----
    cudaEventRecord(e_fork, 0);
    cudaStreamWaitEvent(s_csr, e_fork, 0);
    zero_deg<<<(N_NODES + 255) / 256, 256, 0, s_csr>>>();
    hist_kernel<<<(N_EDGES / 4 + 255) / 256, 256, 0, s_csr>>>((const int4*)dst);
    scan_kernel<<<1, 1024, 0, s_csr>>>();
    scatter_kernel<<<(N_EDGES / 4 + 255) / 256, 256, 0, s_csr>>>((const int4*)src,
                                                                 (const int4*)dst);
    cudaEventRecord(e_join, s_csr);

    // ---- main stream: GEMM1 (independent of CSR) ----
    gemm_attn<float><<<dim3((N_NODES + 127) / 128, F1 / 64), 128>>>(
        h, W1, p_feat1h, N_NODES, F1, IN_DIM, al1, ar1, p_el1, p_er1, H0);

    // ---- join: aggregation needs both GEMM1 and CSR ----
    cudaStreamWaitEvent(0, e_join, 0);
    node_agg1<<<N_NODES, 128>>>();

    // ---- layer 2 ----
    gemm_attn<__half><<<dim3((N_NODES + 127) / 128, OUT_D / 64), 128>>>(
        p_x1h, W2, p_feat2h, N_NODES, OUT_D, F1, al2, ar2, p_el2, p_er2, 1);
    node_agg2<<<N_NODES, 64>>>(out);
}

// round 16
// speedup vs baseline: 1.2416x; 1.0038x over previous
#include <cuda_runtime.h>
#include <cuda_fp16.h>
#include <math.h>

#define N_NODES 10000
#define N_EDGES 320000
#define IN_DIM  512
#define H0      8
#define D0      64
#define F1      512   /* H0*D0 */
#define OUT_D   64
#define MAXD    128   /* fast-path degree cap (smem); slow path beyond */

// ---------------- scratch (device globals; no allocation allowed) ----------------
__device__ __half g_feat1h[N_NODES * F1];   // h @ W1 (fp16)
__device__ __half g_x1h   [N_NODES * F1];   // layer-1 output (fp16)
__device__ __half g_feat2h[N_NODES * OUT_D];
__device__ float  g_el1  [N_NODES * H0];
__device__ float  g_er1  [N_NODES * H0];
__device__ float  g_el2  [N_NODES];
__device__ float  g_er2  [N_NODES];
__device__ int    g_deg  [N_NODES];
__device__ int    g_cur  [N_NODES];
__device__ int    g_off  [N_NODES + 1];
__device__ int    g_csr  [N_EDGES];         // src ids sorted by dst

// ================= CSR build =================
__global__ void zero_deg(void) {
    int i = blockIdx.x * blockDim.x + threadIdx.x;
    if (i < N_NODES) g_deg[i] = 0;
}

__global__ void hist_kernel(const int4* __restrict__ dst4) {
    int i = blockIdx.x * blockDim.x + threadIdx.x;
    if (i < N_EDGES / 4) {
        int4 d = dst4[i];
        atomicAdd(&g_deg[d.x], 1);
        atomicAdd(&g_deg[d.y], 1);
        atomicAdd(&g_deg[d.z], 1);
        atomicAdd(&g_deg[d.w], 1);
    }
}

__global__ void __launch_bounds__(1024) scan_kernel(void) {
    __shared__ int part[1024];
    int tid = threadIdx.x;
    int base = tid * 10;
    int sum = 0;
#pragma unroll
    for (int j = 0; j < 10; j++) {
        int idx = base + j;
        if (idx < N_NODES) sum += g_deg[idx];
    }
    part[tid] = sum;
    __syncthreads();
    for (int off = 1; off < 1024; off <<= 1) {
        int v = (tid >= off) ? part[tid - off] : 0;
        __syncthreads();
        part[tid] += v;
        __syncthreads();
    }
    int run = (tid > 0) ? part[tid - 1] : 0;
#pragma unroll
    for (int j = 0; j < 10; j++) {
        int idx = base + j;
        if (idx < N_NODES) {
            int v = g_deg[idx];
            g_off[idx] = run;
            g_cur[idx] = run;
            run += v;
        }
    }
    if (tid == 1023) g_off[N_NODES] = part[1023];
}

__global__ void scatter_kernel(const int4* __restrict__ src4, const int4* __restrict__ dst4) {
    int i = blockIdx.x * blockDim.x + threadIdx.x;
    if (i < N_EDGES / 4) {
        int4 s = src4[i];
        int4 d = dst4[i];
        int p0 = atomicAdd(&g_cur[d.x], 1);
        int p1 = atomicAdd(&g_cur[d.y], 1);
        int p2 = atomicAdd(&g_cur[d.z], 1);
        int p3 = atomicAdd(&g_cur[d.w], 1);
        g_csr[p0] = s.x; g_csr[p1] = s.y; g_csr[p2] = s.z; g_csr[p3] = s.w;
    }
}

// ================= fp16 tensor-core GEMM + fused attention-logit epilogue =====
// C[M,N](fp16) = A[M,K] @ B[K,N];  BM=128, BN=64, BK=16; 128 thr = 4 warps (2x2).
// mma.sync.m16n8k16.f16 with fp32 accumulate (fp16 mantissa == tf32 mantissa).
// BN == head dim (64): block (m0, hh) holds head hh fully -> epilogue reduces
// el/er = feat . attn_{l,r}[hh] for its 128 rows.

template<typename AT>
__device__ __forceinline__ void load_tiles(
    const AT* __restrict__ A, const float* __restrict__ B,
    int M, int N, int K, int m0, int n0, int k0,
    int arow, int acol, int brow, int bcol, uint2* pa, float4* pb)
{
#pragma unroll
    for (int j = 0; j < 4; j++) {
        int r = m0 + arow + j * 32;
        if (r < M) {
            if constexpr (sizeof(AT) == 4) {
                float4 v = *(const float4*)&A[(size_t)r * K + k0 + acol];
                __half2 h0 = __floats2half2_rn(v.x, v.y);
                __half2 h1 = __floats2half2_rn(v.z, v.w);
                pa[j].x = *reinterpret_cast<unsigned*>(&h0);
                pa[j].y = *reinterpret_cast<unsigned*>(&h1);
            } else {
                pa[j] = *(const uint2*)&A[(size_t)r * K + k0 + acol];
            }
        } else pa[j] = make_uint2(0u, 0u);
    }
#pragma unroll
    for (int j = 0; j < 2; j++)
        pb[j] = *(const float4*)&B[(size_t)(k0 + brow) * N + n0 + bcol + j * 4];
}

template<typename AT>
__global__ void __launch_bounds__(128)
gemm_attn(const AT* __restrict__ A, const float* __restrict__ B,
          __half* __restrict__ C, int M, int N, int K,
          const float* __restrict__ al, const float* __restrict__ ar,
          float* __restrict__ el_out, float* __restrict__ er_out, int Hs)
{
    // As: half2 words, [m][k2] (k2 = k/2, 8 words + 1 pad)
    // Bs: halfs, [n][k] (16 + 2 pad) -> b-fragments load as half2 along k
    __shared__ unsigned As[2][128][9];
    __shared__ __half   Bs[2][64][18];
    __shared__ float s_el[2][128], s_er[2][128];
    const int tid  = threadIdx.x;
    const int lane = tid & 31, warp = tid >> 5;
    const int wm = warp >> 1, wn = warp & 1;
    const int gid = lane >> 2, tig = lane & 3;
    const int m0 = blockIdx.x * 128, n0 = blockIdx.y * 64;
    const int hh = blockIdx.y;   // head index (BN == head dim)

    const int arow = tid >> 2;           // 0..31 (+j*32)
    const int acol = (tid & 3) * 4;      // k offset (elements)
    const int ac2  = (tid & 3) * 2;      // k offset (half2 words)
    const int brow = tid >> 3;           // 0..15  (k index)
    const int bcol = (tid & 7) * 8;      // 0..56  (n offset)

    float acc[4][4][4];
#pragma unroll
    for (int mi = 0; mi < 4; mi++)
#pragma unroll
        for (int ni = 0; ni < 4; ni++)
#pragma unroll
            for (int q = 0; q < 4; q++) acc[mi][ni][q] = 0.f;

    uint2 pa[4]; float4 pb[2];
    load_tiles<AT>(A, B, M, N, K, m0, n0, 0, arow, acol, brow, bcol, pa, pb);
#pragma unroll
    for (int j = 0; j < 4; j++) {
        int r = arow + j * 32;
        As[0][r][ac2 + 0] = pa[j].x;
        As[0][r][ac2 + 1] = pa[j].y;
    }
#pragma unroll
    for (int j = 0; j < 2; j++) {
        Bs[0][bcol + j * 4 + 0][brow] = __float2half(pb[j].x);
        Bs[0][bcol + j * 4 + 1][brow] = __float2half(pb[j].y);
        Bs[0][bcol + j * 4 + 2][brow] = __float2half(pb[j].z);
        Bs[0][bcol + j * 4 + 3][brow] = __float2half(pb[j].w);
    }
    __syncthreads();

    int cur = 0;
    for (int k0 = 0; k0 < K; k0 += 16) {
        const bool more = (k0 + 16 < K);
        if (more)
            load_tiles<AT>(A, B, M, N, K, m0, n0, k0 + 16, arow, acol, brow, bcol, pa, pb);

        unsigned af[4][4], bf[4][2];
#pragma unroll
        for (int mi = 0; mi < 4; mi++) {
            int r = wm * 64 + mi * 16 + gid;
            af[mi][0] = As[cur][r    ][tig];
            af[mi][1] = As[cur][r + 8][tig];
            af[mi][2] = As[cur][r    ][tig + 4];
            af[mi][3] = As[cur][r + 8][tig + 4];
        }
#pragma unroll
        for (int ni = 0; ni < 4; ni++) {
            int c = wn * 32 + ni * 8 + gid;
            bf[ni][0] = *(const unsigned*)&Bs[cur][c][2 * tig];
            bf[ni][1] = *(const unsigned*)&Bs[cur][c][2 * tig + 8];
        }
#pragma unroll
        for (int mi = 0; mi < 4; mi++)
#pragma unroll
            for (int ni = 0; ni < 4; ni++) {
                asm volatile(
                    "mma.sync.aligned.m16n8k16.row.col.f32.f16.f16.f32 "
                    "{%0,%1,%2,%3}, {%4,%5,%6,%7}, {%8,%9}, {%0,%1,%2,%3};"
                    : "+f"(acc[mi][ni][0]), "+f"(acc[mi][ni][1]),
                      "+f"(acc[mi][ni][2]), "+f"(acc[mi][ni][3])
                    : "r"(af[mi][0]), "r"(af[mi][1]), "r"(af[mi][2]), "r"(af[mi][3]),
                      "r"(bf[ni][0]), "r"(bf[ni][1]));
            }

        if (more) {
            int nxt = cur ^ 1;
#pragma unroll
            for (int j = 0; j < 4; j++) {
                int r = arow + j * 32;
                As[nxt][r][ac2 + 0] = pa[j].x;
                As[nxt][r][ac2 + 1] = pa[j].y;
            }
#pragma unroll
            for (int j = 0; j < 2; j++) {
                Bs[nxt][bcol + j * 4 + 0][brow] = __float2half(pb[j].x);
                Bs[nxt][bcol + j * 4 + 1][brow] = __float2half(pb[j].y);
                Bs[nxt][bcol + j * 4 + 2][brow] = __float2half(pb[j].z);
                Bs[nxt][bcol + j * 4 + 3][brow] = __float2half(pb[j].w);
            }
            __syncthreads();
            cur = nxt;
        }
    }

    // ---- C store (fp16) ----
#pragma unroll
    for (int mi = 0; mi < 4; mi++)
#pragma unroll
        for (int ni = 0; ni < 4; ni++) {
            int r = m0 + wm * 64 + mi * 16 + gid;
            int c = n0 + wn * 32 + ni * 8 + 2 * tig;
            if (r < M)
                *(__half2*)&C[(size_t)r * N + c] =
                    __floats2half2_rn(acc[mi][ni][0], acc[mi][ni][1]);
            if (r + 8 < M)
                *(__half2*)&C[(size_t)(r + 8) * N + c] =
                    __floats2half2_rn(acc[mi][ni][2], acc[mi][ni][3]);
        }

    // ---- fused attention logits: el/er = feat . attn_{l,r}[hh] ----
#pragma unroll
    for (int mi = 0; mi < 4; mi++) {
        float el0 = 0.f, er0 = 0.f, el1 = 0.f, er1 = 0.f;
#pragma unroll
        for (int ni = 0; ni < 4; ni++) {
            int cl = wn * 32 + ni * 8 + 2 * tig;
            float A0 = al[hh * 64 + cl], A1 = al[hh * 64 + cl + 1];
            float R0 = ar[hh * 64 + cl], R1 = ar[hh * 64 + cl + 1];
            el0 = fmaf(acc[mi][ni][0], A0, fmaf(acc[mi][ni][1], A1, el0));
            er0 = fmaf(acc[mi][ni][0], R0, fmaf(acc[mi][ni][1], R1, er0));
            el1 = fmaf(acc[mi][ni][2], A0, fmaf(acc[mi][ni][3], A1, el1));
            er1 = fmaf(acc[mi][ni][2], R0, fmaf(acc[mi][ni][3], R1, er1));
        }
#pragma unroll
        for (int o = 1; o <= 2; o <<= 1) {
            el0 += __shfl_xor_sync(0xffffffffu, el0, o);
            er0 += __shfl_xor_sync(0xffffffffu, er0, o);
            el1 += __shfl_xor_sync(0xffffffffu, el1, o);
            er1 += __shfl_xor_sync(0xffffffffu, er1, o);
        }
        if (tig == 0) {
            int r = wm * 64 + mi * 16 + gid;
            s_el[wn][r]     = el0;  s_er[wn][r]     = er0;
            s_el[wn][r + 8] = el1;  s_er[wn][r + 8] = er1;
        }
    }
    __syncthreads();
    {
        int r = tid;
        if (m0 + r < M) {
            el_out[(size_t)(m0 + r) * Hs + hh] = s_el[0][r] + s_el[1][r];
            er_out[(size_t)(m0 + r) * Hs + hh] = s_er[0][r] + s_er[1][r];
        }
    }
}

// ================= fused per-node aggregation, layer 1 =================
__global__ void __launch_bounds__(128)
node_agg1(void) {
    int n   = blockIdx.x;
    int tid = threadIdx.x;
    __shared__ int   s_src[MAXD];
    __shared__ float s_w[MAXD][H0];
    __shared__ float s_red[16][H0];
    __shared__ float s_mh[H0], s_inv[H0], s_er[H0];
    int beg = g_off[n], deg = g_off[n + 1] - beg;
    if (tid < 8) s_er[tid] = g_er1[n * H0 + tid];

    if (deg <= MAXD) {
        if (tid < deg) s_src[tid] = g_csr[beg + tid];
        __syncthreads();
        int h = tid & 7, r = tid >> 3;   // r in 0..15
        float lmax = -1e30f;
        for (int j = r; j < deg; j += 16) {
            float x = g_el1[s_src[j] * H0 + h] + s_er[h];
            x = x > 0.f ? x : 0.2f * x;
            s_w[j][h] = x;
            lmax = fmaxf(lmax, x);
        }
        s_red[r][h] = lmax;
        __syncthreads();
        if (tid < 8) {
            float m = s_red[0][tid];
#pragma unroll
            for (int q = 1; q < 16; q++) m = fmaxf(m, s_red[q][tid]);
            s_mh[tid] = m;
        }
        __syncthreads();
        float mh = s_mh[h];
        float lsum = 0.f;
        for (int j = r; j < deg; j += 16) {
            float w = __expf(s_w[j][h] - mh);
            s_w[j][h] = w;
            lsum += w;
        }
        s_red[r][h] = lsum;
        __syncthreads();
        if (tid < 8) {
            float s = 0.f;
#pragma unroll
            for (int q = 0; q < 16; q++) s += s_red[q][tid];
            s_inv[tid] = (deg > 0) ? 1.f / s : 0.f;
        }
        __syncthreads();

        int h2 = tid >> 4;
        const int col = tid * 4;
        float4 acc = make_float4(0.f, 0.f, 0.f, 0.f);
#pragma unroll 4
        for (int j = 0; j < deg; j++) {
            float w = s_w[j][h2];
            uint2 u = *(const uint2*)&g_feat1h[(size_t)s_src[j] * F1 + col];
            float2 f0 = __half22float2(*reinterpret_cast<__half2*>(&u.x));
            float2 f1 = __half22float2(*reinterpret_cast<__half2*>(&u.y));
            acc.x = fmaf(w, f0.x, acc.x);
            acc.y = fmaf(w, f0.y, acc.y);
            acc.z = fmaf(w, f1.x, acc.z);
            acc.w = fmaf(w, f1.y, acc.w);
        }
        float inv = s_inv[h2];
        float4 o;
        o.x = acc.x * inv; o.y = acc.y * inv; o.z = acc.z * inv; o.w = acc.w * inv;
        o.x = o.x > 0.f ? o.x : expm1f(o.x);
        o.y = o.y > 0.f ? o.y : expm1f(o.y);
        o.z = o.z > 0.f ? o.z : expm1f(o.z);
        o.w = o.w > 0.f ? o.w : expm1f(o.w);
        uint2 uo;
        *reinterpret_cast<__half2*>(&uo.x) = __floats2half2_rn(o.x, o.y);
        *reinterpret_cast<__half2*>(&uo.y) = __floats2half2_rn(o.z, o.w);
        *(uint2*)&g_x1h[(size_t)n * F1 + col] = uo;
    } else {
        __syncthreads();
        const int* sp = g_csr + beg;
        int h = tid >> 4;
        float erh = s_er[h];
        float m = -1e30f;
        for (int j = 0; j < deg; j++) {
            float x = g_el1[sp[j] * H0 + h] + erh;
            x = x > 0.f ? x : 0.2f * x;
            m = fmaxf(m, x);
        }
        float4 acc = make_float4(0.f, 0.f, 0.f, 0.f);
        float s = 0.f;
        const int col = tid * 4;
        for (int j = 0; j < deg; j++) {
            int si = sp[j];
            float x = g_el1[si * H0 + h] + erh;
            x = x > 0.f ? x : 0.2f * x;
            float w = __expf(x - m);
            s += w;
            uint2 u = *(const uint2*)&g_feat1h[(size_t)si * F1 + col];
            float2 f0 = __half22float2(*reinterpret_cast<__half2*>(&u.x));
            float2 f1 = __half22float2(*reinterpret_cast<__half2*>(&u.y));
            acc.x = fmaf(w, f0.x, acc.x);
            acc.y = fmaf(w, f0.y, acc.y);
            acc.z = fmaf(w, f1.x, acc.z);
            acc.w = fmaf(w, f1.y, acc.w);
        }
        float inv = 1.f / s;
        float4 o;
        o.x = acc.x * inv; o.y = acc.y * inv; o.z = acc.z * inv; o.w = acc.w * inv;
        o.x = o.x > 0.f ? o.x : expm1f(o.x);
        o.y = o.y > 0.f ? o.y : expm1f(o.y);
        o.z = o.z > 0.f ? o.z : expm1f(o.z);
        o.w = o.w > 0.f ? o.w : expm1f(o.w);
        uint2 uo;
        *reinterpret_cast<__half2*>(&uo.x) = __floats2half2_rn(o.x, o.y);
        *reinterpret_cast<__half2*>(&uo.y) = __floats2half2_rn(o.z, o.w);
        *(uint2*)&g_x1h[(size_t)n * F1 + col] = uo;
    }
}

// ================= fused per-node aggregation, layer 2 (writes d_out) =================
__global__ void __launch_bounds__(64)
node_agg2(float* __restrict__ out) {
    int n = blockIdx.x, tid = threadIdx.x;
    __shared__ int   s_src[MAXD];
    __shared__ float s_w[MAXD];
    __shared__ float s_red[2];
    int beg = g_off[n], deg = g_off[n + 1] - beg;
    float er = g_er2[n];

    if (deg <= MAXD) {
        for (int i = tid; i < deg; i += 64) s_src[i] = g_csr[beg + i];
        __syncthreads();
        float lmax = -1e30f;
        for (int j = tid; j < deg; j += 64) {
            float x = g_el2[s_src[j]] + er;
            x = x > 0.f ? x : 0.2f * x;
            s_w[j] = x;
            lmax = fmaxf(lmax, x);
        }
#pragma unroll
        for (int o = 16; o > 0; o >>= 1)
            lmax = fmaxf(lmax, __shfl_xor_sync(0xffffffffu, lmax, o));
        if ((tid & 31) == 0) s_red[tid >> 5] = lmax;
        __syncthreads();
        float m = fmaxf(s_red[0], s_red[1]);
        float lsum = 0.f;
        for (int j = tid; j < deg; j += 64) {
            float w = __expf(s_w[j] - m);
            s_w[j] = w;
            lsum += w;
        }
#pragma unroll
        for (int o = 16; o > 0; o >>= 1)
            lsum += __shfl_xor_sync(0xffffffffu, lsum, o);
        if ((tid & 31) == 0) s_red[tid >> 5] = lsum;
        __syncthreads();
        float s = s_red[0] + s_red[1];

        float acc = 0.f;
#pragma unroll 4
        for (int j = 0; j < deg; j++)
            acc = fmaf(s_w[j], __half2float(g_feat2h[(size_t)s_src[j] * OUT_D + tid]), acc);
        out[(size_t)n * OUT_D + tid] = (deg > 0) ? acc / s : 0.f;
    } else {
        __syncthreads();
        const int* sp = g_csr + beg;
        float m = -1e30f;
        for (int j = 0; j < deg; j++) {
            float x = g_el2[sp[j]] + er;
            x = x > 0.f ? x : 0.2f * x;
            m = fmaxf(m, x);
        }
        float acc = 0.f, s = 0.f;
        for (int j = 0; j < deg; j++) {
            int si = sp[j];
            float x = g_el2[si] + er;
            x = x > 0.f ? x : 0.2f * x;
            float w = __expf(x - m);
            s += w;
            acc = fmaf(w, __half2float(g_feat2h[(size_t)si * OUT_D + tid]), acc);
        }
        out[(size_t)n * OUT_D + tid] = acc / s;
    }
}

// ================= launch =================
extern "C" void kernel_launch(void* const* d_in, const int* in_sizes, int n_in,
                              void* d_out, int out_size) {
    (void)in_sizes; (void)n_in; (void)out_size;
    const float* h   = (const float*)d_in[0];
    const int*   src = (const int*)  d_in[1];
    const int*   dst = (const int*)  d_in[2];
    const float* W1  = (const float*)d_in[3];
    const float* al1 = (const float*)d_in[4];
    const float* ar1 = (const float*)d_in[5];
    const float* W2  = (const float*)d_in[6];
    const float* al2 = (const float*)d_in[7];
    const float* ar2 = (const float*)d_in[8];
    float* out = (float*)d_out;

    __half *p_feat1h, *p_x1h, *p_feat2h;
    float *p_el1, *p_er1, *p_el2, *p_er2;
    cudaGetSymbolAddress((void**)&p_feat1h, g_feat1h);
    cudaGetSymbolAddress((void**)&p_x1h,    g_x1h);
    cudaGetSymbolAddress((void**)&p_feat2h, g_feat2h);
    cudaGetSymbolAddress((void**)&p_el1,    g_el1);
    cudaGetSymbolAddress((void**)&p_er1,    g_er1);
    cudaGetSymbolAddress((void**)&p_el2,    g_el2);
    cudaGetSymbolAddress((void**)&p_er2,    g_er2);

    // One-time host-side resources for forked capture (no device memory).
    static cudaStream_t s_csr = 0;
    static cudaEvent_t  e_fork = 0, e_join = 0;
    if (s_csr == 0) {
        cudaStreamCreateWithFlags(&s_csr, cudaStreamNonBlocking);
        cudaEventCreateWithFlags(&e_fork, cudaEventDisableTiming);
        cudaEventCreateWithFlags(&e_join, cudaEventDisableTiming);
    }

    // ---- fork: CSR build on side stream, concurrent with GEMM1 ----
    cudaEventRecord(e_fork, 0);
    cudaStreamWaitEvent(s_csr, e_fork, 0);
    zero_deg<<<(N_NODES + 255) / 256, 256, 0, s_csr>>>();
    hist_kernel<<<(N_EDGES / 4 + 255) / 256, 256, 0, s_csr>>>((const int4*)dst);
    scan_kernel<<<1, 1024, 0, s_csr>>>();
    scatter_kernel<<<(N_EDGES / 4 + 255) / 256, 256, 0, s_csr>>>((const int4*)src,
                                                                 (const int4*)dst);
    cudaEventRecord(e_join, s_csr);

    // ---- main stream: GEMM1 (independent of CSR) ----
    gemm_attn<float><<<dim3((N_NODES + 127) / 128, F1 / 64), 128>>>(
        h, W1, p_feat1h, N_NODES, F1, IN_DIM, al1, ar1, p_el1, p_er1, H0);

    // ---- join: aggregation needs both GEMM1 and CSR ----
    cudaStreamWaitEvent(0, e_join, 0);
    node_agg1<<<N_NODES, 128>>>();

    // ---- layer 2 ----
    gemm_attn<__half><<<dim3((N_NODES + 127) / 128, OUT_D / 64), 128>>>(
        p_x1h, W2, p_feat2h, N_NODES, OUT_D, F1, al2, ar2, p_el2, p_er2, 1);
    node_agg2<<<N_NODES, 64>>>(out);
}